// round 1
// baseline (speedup 1.0000x reference)
#include <cuda_runtime.h>
#include <math.h>

#define NTOK 2048   // B*N
#define DMODEL 1024
#define NSEQ 1024
#define NB 2
#define NH 16
#define HD 64

// Output layout (float32, concatenated in reference return order)
#define OFF_FIN 0
#define OFF_FWD 2097152
#define OFF_BWD 2099200
#define OFF_STR 2101248

// scratch (device globals — no runtime allocation allowed)
__device__ float g_HF[NTOK * DMODEL];       // head_features, [token][h*64+e]
__device__ float g_multi[NTOK * DMODEL];    // fused head outputs
__device__ float g_partial[4][NB][DMODEL];  // column-sum partials
__device__ float g_cvec[NB][NH][HD];        // W1_mid_sum @ mean + b1

// ---------------------------------------------------------------------------
// SGEMM: C[m][n] = sum_k A[m][k] * W[n][k]   (NT form; all dims multiples of tile)
// ---------------------------------------------------------------------------
#define BM 128
#define BN 128
#define BKK 16

__global__ __launch_bounds__(256) void sgemm_nt(
    const float* __restrict__ A, const float* __restrict__ W,
    float* __restrict__ C, int M, int Nn, int K)
{
    __shared__ float As[BKK][BM + 4];
    __shared__ float Bs[BKK][BN + 4];

    const int tid = threadIdx.x;
    const int m0 = blockIdx.y * BM;
    const int n0 = blockIdx.x * BN;

    const int lr = tid >> 2;          // 0..63
    const int lc = (tid & 3) << 2;    // 0,4,8,12

    const int tr = tid >> 4;          // 0..15
    const int tc = tid & 15;          // 0..15

    float acc[8][8];
#pragma unroll
    for (int i = 0; i < 8; ++i)
#pragma unroll
        for (int j = 0; j < 8; ++j) acc[i][j] = 0.0f;

    for (int k0 = 0; k0 < K; k0 += BKK) {
#pragma unroll
        for (int s = 0; s < 2; ++s) {
            int row = lr + s * 64;
            float4 av = *(const float4*)(A + (size_t)(m0 + row) * K + k0 + lc);
            As[lc + 0][row] = av.x;
            As[lc + 1][row] = av.y;
            As[lc + 2][row] = av.z;
            As[lc + 3][row] = av.w;
            float4 bv = *(const float4*)(W + (size_t)(n0 + row) * K + k0 + lc);
            Bs[lc + 0][row] = bv.x;
            Bs[lc + 1][row] = bv.y;
            Bs[lc + 2][row] = bv.z;
            Bs[lc + 3][row] = bv.w;
        }
        __syncthreads();

#pragma unroll
        for (int k = 0; k < BKK; ++k) {
            float4 a0 = *(const float4*)&As[k][tr * 8];
            float4 a1 = *(const float4*)&As[k][tr * 8 + 4];
            float4 b0 = *(const float4*)&Bs[k][tc * 8];
            float4 b1 = *(const float4*)&Bs[k][tc * 8 + 4];
            float ra[8] = {a0.x, a0.y, a0.z, a0.w, a1.x, a1.y, a1.z, a1.w};
            float rb[8] = {b0.x, b0.y, b0.z, b0.w, b1.x, b1.y, b1.z, b1.w};
#pragma unroll
            for (int i = 0; i < 8; ++i)
#pragma unroll
                for (int j = 0; j < 8; ++j)
                    acc[i][j] = fmaf(ra[i], rb[j], acc[i][j]);
        }
        __syncthreads();
    }

#pragma unroll
    for (int i = 0; i < 8; ++i) {
        int row = m0 + tr * 8 + i;
        float4 o0 = make_float4(acc[i][0], acc[i][1], acc[i][2], acc[i][3]);
        float4 o1 = make_float4(acc[i][4], acc[i][5], acc[i][6], acc[i][7]);
        *(float4*)(C + (size_t)row * Nn + n0 + tc * 8) = o0;
        *(float4*)(C + (size_t)row * Nn + n0 + tc * 8 + 4) = o1;
    }
}

// ---------------------------------------------------------------------------
// Column partial sums of g_HF per batch (for the sequence mean)
// grid (8, NB, 4), block 128
// ---------------------------------------------------------------------------
__global__ void colmean_kernel()
{
    int c = blockIdx.x * 128 + threadIdx.x;
    int b = blockIdx.y;
    int r = blockIdx.z;
    const float* base = g_HF + (size_t)(b * NSEQ + r * 256) * DMODEL + c;
    float s = 0.0f;
#pragma unroll 4
    for (int row = 0; row < 256; ++row)
        s += base[(size_t)row * DMODEL];
    g_partial[r][b][c] = s;
}

// ---------------------------------------------------------------------------
// cvec[b][h][j] = sum_e (W1[h,j,64+e] + W1[h,j,128+e]) * mean[b][h*64+e] + b1[h,j]
// grid (NH, NB), block 64
// ---------------------------------------------------------------------------
__global__ void cvec_kernel(const float* __restrict__ fuW1,
                            const float* __restrict__ fub1)
{
    __shared__ float mn[HD];
    int h = blockIdx.x, b = blockIdx.y, j = threadIdx.x;
    int c = h * HD + j;
    mn[j] = (g_partial[0][b][c] + g_partial[1][b][c] +
             g_partial[2][b][c] + g_partial[3][b][c]) * (1.0f / 1024.0f);
    __syncthreads();
    const float* wrow = fuW1 + (size_t)(h * HD + j) * (3 * HD);
    float acc = fub1[h * HD + j];
#pragma unroll
    for (int e = 0; e < HD; ++e)
        acc = fmaf(wrow[64 + e] + wrow[128 + e], mn[e], acc);
    g_cvec[b][h][j] = acc;
}

// ---------------------------------------------------------------------------
// Fusion MLP: per head, two 32x64x64 GEMMs with exact GELU between.
// Block handles 32 tokens; grid 64 blocks; 256 threads.
// ---------------------------------------------------------------------------
__device__ __forceinline__ float gelu_exact(float x) {
    return 0.5f * x * (1.0f + erff(x * 0.70710678118654752f));
}

__global__ __launch_bounds__(256) void fusion_kernel(
    const float* __restrict__ fuW1, const float* __restrict__ fuW2,
    const float* __restrict__ fub2)
{
    __shared__ float aT[HD][36];   // [e][t]  hf transposed
    __shared__ float bT[HD][68];   // [e][j] stage1 weights / [j][f] stage2 weights
    __shared__ float tsT[HD][36];  // [j][t]  gelu output transposed

    const int tid = threadIdx.x;
    const int m0 = blockIdx.x * 32;
    const int b = m0 >> 10;
    const int tr = tid >> 4;   // 0..15 -> tokens 2tr..2tr+1
    const int tc = tid & 15;   // 0..15 -> cols 4tc..4tc+3

    for (int h = 0; h < NH; ++h) {
        // load hf tile transposed
        for (int idx = tid; idx < 32 * 64; idx += 256) {
            int t = idx >> 6, e = idx & 63;
            aT[e][t] = g_HF[(size_t)(m0 + t) * DMODEL + h * HD + e];
        }
        // load W1a transposed: bT[e][j] = fuW1[h, j, e]
        for (int idx = tid; idx < 64 * 64; idx += 256) {
            int j = idx >> 6, e = idx & 63;
            bT[e][j] = fuW1[(size_t)(h * HD + j) * (3 * HD) + e];
        }
        __syncthreads();

        float acc[2][4] = {{0, 0, 0, 0}, {0, 0, 0, 0}};
#pragma unroll
        for (int e = 0; e < HD; ++e) {
            float a0 = aT[e][tr * 2];
            float a1 = aT[e][tr * 2 + 1];
            float4 bv = *(const float4*)&bT[e][tc * 4];
            acc[0][0] = fmaf(a0, bv.x, acc[0][0]);
            acc[0][1] = fmaf(a0, bv.y, acc[0][1]);
            acc[0][2] = fmaf(a0, bv.z, acc[0][2]);
            acc[0][3] = fmaf(a0, bv.w, acc[0][3]);
            acc[1][0] = fmaf(a1, bv.x, acc[1][0]);
            acc[1][1] = fmaf(a1, bv.y, acc[1][1]);
            acc[1][2] = fmaf(a1, bv.z, acc[1][2]);
            acc[1][3] = fmaf(a1, bv.w, acc[1][3]);
        }
#pragma unroll
        for (int i = 0; i < 2; ++i)
#pragma unroll
            for (int jj = 0; jj < 4; ++jj) {
                int j = tc * 4 + jj;
                float x = acc[i][jj] + g_cvec[b][h][j];
                tsT[j][tr * 2 + i] = gelu_exact(x);
            }
        __syncthreads();

        // load W2: bT[j][f] = fuW2[h, f, j]
        for (int idx = tid; idx < 64 * 64; idx += 256) {
            int f = idx >> 6, j = idx & 63;
            bT[j][f] = fuW2[(size_t)(h * HD + f) * HD + j];
        }
        __syncthreads();

        float acc2[2][4] = {{0, 0, 0, 0}, {0, 0, 0, 0}};
#pragma unroll
        for (int j = 0; j < HD; ++j) {
            float a0 = tsT[j][tr * 2];
            float a1 = tsT[j][tr * 2 + 1];
            float4 bv = *(const float4*)&bT[j][tc * 4];
            acc2[0][0] = fmaf(a0, bv.x, acc2[0][0]);
            acc2[0][1] = fmaf(a0, bv.y, acc2[0][1]);
            acc2[0][2] = fmaf(a0, bv.z, acc2[0][2]);
            acc2[0][3] = fmaf(a0, bv.w, acc2[0][3]);
            acc2[1][0] = fmaf(a1, bv.x, acc2[1][0]);
            acc2[1][1] = fmaf(a1, bv.y, acc2[1][1]);
            acc2[1][2] = fmaf(a1, bv.z, acc2[1][2]);
            acc2[1][3] = fmaf(a1, bv.w, acc2[1][3]);
        }
#pragma unroll
        for (int i = 0; i < 2; ++i) {
            int t = tr * 2 + i;
            float4 o;
            o.x = acc2[i][0] + fub2[h * HD + tc * 4 + 0];
            o.y = acc2[i][1] + fub2[h * HD + tc * 4 + 1];
            o.z = acc2[i][2] + fub2[h * HD + tc * 4 + 2];
            o.w = acc2[i][3] + fub2[h * HD + tc * 4 + 3];
            *(float4*)&g_multi[(size_t)(m0 + t) * DMODEL + h * HD + tc * 4] = o;
        }
        __syncthreads();
    }
}

// ---------------------------------------------------------------------------
// Trivial outputs: fwd/bwd targets + avg_strength (all analytic constants)
// ---------------------------------------------------------------------------
__global__ void extras_kernel(const int* __restrict__ prev,
                              const float* __restrict__ cr,
                              float* __restrict__ out)
{
    int idx = blockIdx.x * blockDim.x + threadIdx.x;
    if (idx >= NTOK) return;
    int n = idx & (NSEQ - 1);

    // uniform softmax over N equal logits -> targets = int(511.5) = 511
    float thr = floorf((float)NSEQ / (1.0f + expf(-cr[0])));
    float fwd = 511.0f;
    if ((float)n >= thr) {
        int p = prev[idx];
        p = p < 0 ? 0 : (p > NSEQ - 1 ? NSEQ - 1 : p);
        fwd = (float)p;
    }
    out[OFF_FWD + idx] = fwd;
    out[OFF_BWD + idx] = 511.0f;
    // strength = 1 - sum(p*log(p+eps)) with p = 1/N exactly
    out[OFF_STR + idx] = 1.0f - logf(1.0f / (float)NSEQ + 1e-8f);
}

// ---------------------------------------------------------------------------
extern "C" void kernel_launch(void* const* d_in, const int* in_sizes, int n_in,
                              void* d_out, int out_size)
{
    const float* h    = (const float*)d_in[0];
    const int*   prev = (const int*)d_in[1];
    // d_in[2..9]: forward/backward encoder weights — provably dead code
    const float* Wv   = (const float*)d_in[10];
    const float* fuW1 = (const float*)d_in[11];
    const float* fub1 = (const float*)d_in[12];
    const float* fuW2 = (const float*)d_in[13];
    const float* fub2 = (const float*)d_in[14];
    const float* Wo   = (const float*)d_in[15];
    const float* cr   = (const float*)d_in[16];
    float* out = (float*)d_out;

    float *pHF = nullptr, *pMulti = nullptr;
    cudaGetSymbolAddress((void**)&pHF, g_HF);
    cudaGetSymbolAddress((void**)&pMulti, g_multi);

    // 1) head_features[token][h*64+e] = h @ Wv^T
    dim3 g1(DMODEL / BN, NTOK / BM);
    sgemm_nt<<<g1, 256>>>(h, Wv, pHF, NTOK, DMODEL, DMODEL);

    // 2) sequence-mean partials per batch
    colmean_kernel<<<dim3(DMODEL / 128, NB, 4), 128>>>();

    // 3) constant part of fusion stage-1
    cvec_kernel<<<dim3(NH, NB), HD>>>(fuW1, fub1);

    // 4) fusion MLP -> g_multi
    fusion_kernel<<<NTOK / 32, 256>>>(fuW1, fuW2, fub2);

    // 5) final_output = multi @ Wo^T  (written straight to d_out)
    sgemm_nt<<<g1, 256>>>(pMulti, Wo, out, NTOK, DMODEL, DMODEL);

    // 6) analytic outputs
    extras_kernel<<<(NTOK + 255) / 256, 256>>>(prev, cr, out);
}

// round 2
// speedup vs baseline: 1.1868x; 1.1868x over previous
#include <cuda_runtime.h>
#include <math.h>

#define NTOK 2048   // B*N
#define DMODEL 1024
#define NSEQ 1024
#define NB 2
#define NH 16
#define HD 64

// Output layout (float32, concatenated in reference return order)
#define OFF_FIN 0
#define OFF_FWD 2097152
#define OFF_BWD 2099200
#define OFF_STR 2101248

// scratch (device globals — no runtime allocation allowed)
__device__ float g_HF[NTOK * DMODEL];       // head_features, [token][h*64+e]
__device__ float g_multi[NTOK * DMODEL];    // fused head outputs
__device__ float g_partial[4][NB][DMODEL];  // column-sum partials
__device__ float g_cvec[NB][NH][HD];        // W1_mid_sum @ mean + b1

// ---------------------------------------------------------------------------
// SGEMM: C[m][n] = sum_k A[m][k] * W[n][k]   (NT form; all dims multiples of tile)
// ---------------------------------------------------------------------------
#define BM 128
#define BN 128
#define BKK 16

__global__ __launch_bounds__(256) void sgemm_nt(
    const float* __restrict__ A, const float* __restrict__ W,
    float* __restrict__ C, int M, int Nn, int K)
{
    __shared__ float As[BKK][BM + 4];
    __shared__ float Bs[BKK][BN + 4];

    const int tid = threadIdx.x;
    const int m0 = blockIdx.y * BM;
    const int n0 = blockIdx.x * BN;

    const int lr = tid >> 2;          // 0..63
    const int lc = (tid & 3) << 2;    // 0,4,8,12

    const int tr = tid >> 4;          // 0..15
    const int tc = tid & 15;          // 0..15

    float acc[8][8];
#pragma unroll
    for (int i = 0; i < 8; ++i)
#pragma unroll
        for (int j = 0; j < 8; ++j) acc[i][j] = 0.0f;

    for (int k0 = 0; k0 < K; k0 += BKK) {
#pragma unroll
        for (int s = 0; s < 2; ++s) {
            int row = lr + s * 64;
            float4 av = *(const float4*)(A + (size_t)(m0 + row) * K + k0 + lc);
            As[lc + 0][row] = av.x;
            As[lc + 1][row] = av.y;
            As[lc + 2][row] = av.z;
            As[lc + 3][row] = av.w;
            float4 bv = *(const float4*)(W + (size_t)(n0 + row) * K + k0 + lc);
            Bs[lc + 0][row] = bv.x;
            Bs[lc + 1][row] = bv.y;
            Bs[lc + 2][row] = bv.z;
            Bs[lc + 3][row] = bv.w;
        }
        __syncthreads();

#pragma unroll
        for (int k = 0; k < BKK; ++k) {
            float4 a0 = *(const float4*)&As[k][tr * 8];
            float4 a1 = *(const float4*)&As[k][tr * 8 + 4];
            float4 b0 = *(const float4*)&Bs[k][tc * 8];
            float4 b1 = *(const float4*)&Bs[k][tc * 8 + 4];
            float ra[8] = {a0.x, a0.y, a0.z, a0.w, a1.x, a1.y, a1.z, a1.w};
            float rb[8] = {b0.x, b0.y, b0.z, b0.w, b1.x, b1.y, b1.z, b1.w};
#pragma unroll
            for (int i = 0; i < 8; ++i)
#pragma unroll
                for (int j = 0; j < 8; ++j)
                    acc[i][j] = fmaf(ra[i], rb[j], acc[i][j]);
        }
        __syncthreads();
    }

#pragma unroll
    for (int i = 0; i < 8; ++i) {
        int row = m0 + tr * 8 + i;
        float4 o0 = make_float4(acc[i][0], acc[i][1], acc[i][2], acc[i][3]);
        float4 o1 = make_float4(acc[i][4], acc[i][5], acc[i][6], acc[i][7]);
        *(float4*)(C + (size_t)row * Nn + n0 + tc * 8) = o0;
        *(float4*)(C + (size_t)row * Nn + n0 + tc * 8 + 4) = o1;
    }
}

// ---------------------------------------------------------------------------
// Column partial sums of g_HF per batch (for the sequence mean)
// grid (8, NB, 4), block 128
// ---------------------------------------------------------------------------
__global__ void colmean_kernel()
{
    int c = blockIdx.x * 128 + threadIdx.x;
    int b = blockIdx.y;
    int r = blockIdx.z;
    const float* base = g_HF + (size_t)(b * NSEQ + r * 256) * DMODEL + c;
    float s = 0.0f;
#pragma unroll 4
    for (int row = 0; row < 256; ++row)
        s += base[(size_t)row * DMODEL];
    g_partial[r][b][c] = s;
}

// ---------------------------------------------------------------------------
// cvec[b][h][j] = sum_e (W1[h,j,64+e] + W1[h,j,128+e]) * mean[b][h*64+e] + b1[h,j]
// grid (NH, NB), block 64
// ---------------------------------------------------------------------------
__global__ void cvec_kernel(const float* __restrict__ fuW1,
                            const float* __restrict__ fub1)
{
    __shared__ float mn[HD];
    int h = blockIdx.x, b = blockIdx.y, j = threadIdx.x;
    int c = h * HD + j;
    mn[j] = (g_partial[0][b][c] + g_partial[1][b][c] +
             g_partial[2][b][c] + g_partial[3][b][c]) * (1.0f / 1024.0f);
    __syncthreads();
    const float* wrow = fuW1 + (size_t)(h * HD + j) * (3 * HD);
    float acc = fub1[h * HD + j];
#pragma unroll
    for (int e = 0; e < HD; ++e)
        acc = fmaf(wrow[64 + e] + wrow[128 + e], mn[e], acc);
    g_cvec[b][h][j] = acc;
}

// ---------------------------------------------------------------------------
// Fusion MLP: per (32-token tile, head): two 32x64x64 GEMMs with exact GELU.
// grid (NTOK/32, NH); 256 threads.
// ---------------------------------------------------------------------------
__device__ __forceinline__ float gelu_exact(float x) {
    return 0.5f * x * (1.0f + erff(x * 0.70710678118654752f));
}

__global__ __launch_bounds__(256) void fusion_kernel(
    const float* __restrict__ fuW1, const float* __restrict__ fuW2,
    const float* __restrict__ fub2)
{
    __shared__ float aT[HD][36];   // [e][t]  hf transposed
    __shared__ float bT[HD][68];   // [e][j] stage1 weights / [j][f] stage2 weights
    __shared__ float tsT[HD][36];  // [j][t]  gelu output transposed

    const int tid = threadIdx.x;
    const int m0 = blockIdx.x * 32;
    const int h = blockIdx.y;
    const int b = m0 >> 10;
    const int tr = tid >> 4;   // 0..15 -> tokens 2tr..2tr+1
    const int tc = tid & 15;   // 0..15 -> cols 4tc..4tc+3

    // load hf tile transposed
    for (int idx = tid; idx < 32 * 64; idx += 256) {
        int t = idx >> 6, e = idx & 63;
        aT[e][t] = g_HF[(size_t)(m0 + t) * DMODEL + h * HD + e];
    }
    // load W1a transposed: bT[e][j] = fuW1[h, j, e]
    for (int idx = tid; idx < 64 * 64; idx += 256) {
        int j = idx >> 6, e = idx & 63;
        bT[e][j] = fuW1[(size_t)(h * HD + j) * (3 * HD) + e];
    }
    __syncthreads();

    float acc[2][4] = {{0, 0, 0, 0}, {0, 0, 0, 0}};
#pragma unroll
    for (int e = 0; e < HD; ++e) {
        float a0 = aT[e][tr * 2];
        float a1 = aT[e][tr * 2 + 1];
        float4 bv = *(const float4*)&bT[e][tc * 4];
        acc[0][0] = fmaf(a0, bv.x, acc[0][0]);
        acc[0][1] = fmaf(a0, bv.y, acc[0][1]);
        acc[0][2] = fmaf(a0, bv.z, acc[0][2]);
        acc[0][3] = fmaf(a0, bv.w, acc[0][3]);
        acc[1][0] = fmaf(a1, bv.x, acc[1][0]);
        acc[1][1] = fmaf(a1, bv.y, acc[1][1]);
        acc[1][2] = fmaf(a1, bv.z, acc[1][2]);
        acc[1][3] = fmaf(a1, bv.w, acc[1][3]);
    }
#pragma unroll
    for (int i = 0; i < 2; ++i)
#pragma unroll
        for (int jj = 0; jj < 4; ++jj) {
            int j = tc * 4 + jj;
            float x = acc[i][jj] + g_cvec[b][h][j];
            tsT[j][tr * 2 + i] = gelu_exact(x);
        }
    __syncthreads();

    // load W2: bT[j][f] = fuW2[h, f, j]
    for (int idx = tid; idx < 64 * 64; idx += 256) {
        int f = idx >> 6, j = idx & 63;
        bT[j][f] = fuW2[(size_t)(h * HD + f) * HD + j];
    }
    __syncthreads();

    float acc2[2][4] = {{0, 0, 0, 0}, {0, 0, 0, 0}};
#pragma unroll
    for (int j = 0; j < HD; ++j) {
        float a0 = tsT[j][tr * 2];
        float a1 = tsT[j][tr * 2 + 1];
        float4 bv = *(const float4*)&bT[j][tc * 4];
        acc2[0][0] = fmaf(a0, bv.x, acc2[0][0]);
        acc2[0][1] = fmaf(a0, bv.y, acc2[0][1]);
        acc2[0][2] = fmaf(a0, bv.z, acc2[0][2]);
        acc2[0][3] = fmaf(a0, bv.w, acc2[0][3]);
        acc2[1][0] = fmaf(a1, bv.x, acc2[1][0]);
        acc2[1][1] = fmaf(a1, bv.y, acc2[1][1]);
        acc2[1][2] = fmaf(a1, bv.z, acc2[1][2]);
        acc2[1][3] = fmaf(a1, bv.w, acc2[1][3]);
    }
#pragma unroll
    for (int i = 0; i < 2; ++i) {
        int t = tr * 2 + i;
        float4 o;
        o.x = acc2[i][0] + fub2[h * HD + tc * 4 + 0];
        o.y = acc2[i][1] + fub2[h * HD + tc * 4 + 1];
        o.z = acc2[i][2] + fub2[h * HD + tc * 4 + 2];
        o.w = acc2[i][3] + fub2[h * HD + tc * 4 + 3];
        *(float4*)&g_multi[(size_t)(m0 + t) * DMODEL + h * HD + tc * 4] = o;
    }
}

// ---------------------------------------------------------------------------
// Trivial outputs: fwd/bwd targets + avg_strength (all analytic constants)
// ---------------------------------------------------------------------------
__global__ void extras_kernel(const int* __restrict__ prev,
                              const float* __restrict__ cr,
                              float* __restrict__ out)
{
    int idx = blockIdx.x * blockDim.x + threadIdx.x;
    if (idx >= NTOK) return;
    int n = idx & (NSEQ - 1);

    // uniform softmax over N equal logits -> targets = int(511.5) = 511
    float thr = floorf((float)NSEQ / (1.0f + expf(-cr[0])));
    float fwd = 511.0f;
    if ((float)n >= thr) {
        int p = prev[idx];
        p = p < 0 ? 0 : (p > NSEQ - 1 ? NSEQ - 1 : p);
        fwd = (float)p;
    }
    out[OFF_FWD + idx] = fwd;
    out[OFF_BWD + idx] = 511.0f;
    // strength = 1 - sum(p*log(p+eps)) with p = 1/N exactly
    out[OFF_STR + idx] = 1.0f - logf(1.0f / (float)NSEQ + 1e-8f);
}

// ---------------------------------------------------------------------------
extern "C" void kernel_launch(void* const* d_in, const int* in_sizes, int n_in,
                              void* d_out, int out_size)
{
    const float* h    = (const float*)d_in[0];
    const int*   prev = (const int*)d_in[1];
    // d_in[2..9]: forward/backward encoder weights — provably dead code
    const float* Wv   = (const float*)d_in[10];
    const float* fuW1 = (const float*)d_in[11];
    const float* fub1 = (const float*)d_in[12];
    const float* fuW2 = (const float*)d_in[13];
    const float* fub2 = (const float*)d_in[14];
    const float* Wo   = (const float*)d_in[15];
    const float* cr   = (const float*)d_in[16];
    float* out = (float*)d_out;

    float *pHF = nullptr, *pMulti = nullptr;
    cudaGetSymbolAddress((void**)&pHF, g_HF);
    cudaGetSymbolAddress((void**)&pMulti, g_multi);

    // 1) head_features[token][h*64+e] = h @ Wv^T
    dim3 g1(DMODEL / BN, NTOK / BM);
    sgemm_nt<<<g1, 256>>>(h, Wv, pHF, NTOK, DMODEL, DMODEL);

    // 2) sequence-mean partials per batch
    colmean_kernel<<<dim3(DMODEL / 128, NB, 4), 128>>>();

    // 3) constant part of fusion stage-1
    cvec_kernel<<<dim3(NH, NB), HD>>>(fuW1, fub1);

    // 4) fusion MLP -> g_multi  (parallel over heads now)
    fusion_kernel<<<dim3(NTOK / 32, NH), 256>>>(fuW1, fuW2, fub2);

    // 5) final_output = multi @ Wo^T  (written straight to d_out)
    sgemm_nt<<<g1, 256>>>(pMulti, Wo, out, NTOK, DMODEL, DMODEL);

    // 6) analytic outputs
    extras_kernel<<<(NTOK + 255) / 256, 256>>>(prev, cr, out);
}

// round 5
// speedup vs baseline: 1.8062x; 1.5218x over previous
#include <cuda_runtime.h>
#include <cuda_bf16.h>
#include <math.h>
#include <stdint.h>

#define NTOK 2048   // B*N
#define DMODEL 1024
#define NSEQ 1024
#define NB 2
#define NH 16
#define HD 64
#define K3 (3 * DMODEL)   // extended split-precision K

// Output layout (float32, concatenated in reference return order)
#define OFF_FIN 0
#define OFF_FWD 2097152
#define OFF_BWD 2099200
#define OFF_STR 2101248

// scratch (device globals — no runtime allocation allowed)
__device__ float g_HF[NTOK * DMODEL];                      // head_features fp32
__device__ float g_partial[4][NB][DMODEL];                 // column-sum partials
__device__ float g_cvec[NB][NH][HD];                       // W1_mid_sum @ mean + b1
// split-precision bf16 operands, extended-K layout (rows of length 3*DMODEL)
__device__ alignas(16) __nv_bfloat16 g_hS[NTOK * K3];      // h:  [hi | lo | hi]
__device__ alignas(16) __nv_bfloat16 g_WvS[DMODEL * K3];   // Wv: [hi | hi | lo]
__device__ alignas(16) __nv_bfloat16 g_WoS[DMODEL * K3];   // Wo: [hi | hi | lo]
__device__ alignas(16) __nv_bfloat16 g_multiS[NTOK * K3];  // multi: [hi | lo | hi]

// ---------------------------------------------------------------------------
// fp32 -> split bf16 (hi at k and o_hi2, lo at o_lo) in extended-K rows
// ---------------------------------------------------------------------------
__global__ void split3_kernel(const float* __restrict__ in,
                              __nv_bfloat16* __restrict__ out,
                              int n, int o_lo, int o_hi2)
{
    int i = (blockIdx.x * blockDim.x + threadIdx.x) * 4;
    if (i >= n) return;
    int row = i >> 10;           // K = DMODEL = 1024 per row
    int k = i & 1023;
    float4 v = *(const float4*)(in + i);

    __nv_bfloat16 h0 = __float2bfloat16_rn(v.x);
    __nv_bfloat16 h1 = __float2bfloat16_rn(v.y);
    __nv_bfloat16 h2 = __float2bfloat16_rn(v.z);
    __nv_bfloat16 h3 = __float2bfloat16_rn(v.w);
    __nv_bfloat16 l0 = __float2bfloat16_rn(v.x - __bfloat162float(h0));
    __nv_bfloat16 l1 = __float2bfloat16_rn(v.y - __bfloat162float(h1));
    __nv_bfloat16 l2 = __float2bfloat16_rn(v.z - __bfloat162float(h2));
    __nv_bfloat16 l3 = __float2bfloat16_rn(v.w - __bfloat162float(h3));

    size_t base = (size_t)row * K3 + k;
    __nv_bfloat162 hA = {h0, h1}, hB = {h2, h3};
    __nv_bfloat162 lA = {l0, l1}, lB = {l2, l3};
    *(__nv_bfloat162*)(out + base)              = hA;
    *(__nv_bfloat162*)(out + base + 2)          = hB;
    *(__nv_bfloat162*)(out + base + o_hi2)      = hA;
    *(__nv_bfloat162*)(out + base + o_hi2 + 2)  = hB;
    *(__nv_bfloat162*)(out + base + o_lo)       = lA;
    *(__nv_bfloat162*)(out + base + o_lo + 2)   = lB;
}

// ---------------------------------------------------------------------------
// bf16 tensor-core NT GEMM: C[m][n] = sum_k A[m][k] * W[n][k], fp32 accum/out.
// Tiles: 128x128x32, 256 threads (8 warps in 2x4), warp tile 64x32.
// cp.async double-buffered; ldmatrix fragments; smem row stride 40 bf16 (80B)
// -> 8 ldmatrix row addresses land in 8 distinct 16B segments (conflict-free).
// ---------------------------------------------------------------------------
#define GBM 128
#define GBN 128
#define GBK 32
#define ASTR 40  // bf16 elems per smem row

__device__ __forceinline__ void cp16(uint32_t s, const void* g) {
    asm volatile("cp.async.cg.shared.global [%0], [%1], 16;\n" :: "r"(s), "l"(g));
}

__global__ __launch_bounds__(256, 1) void gemm_bf16_nt(
    const __nv_bfloat16* __restrict__ A, const __nv_bfloat16* __restrict__ W,
    float* __restrict__ C, int M, int Nn, int K)
{
    __shared__ alignas(16) __nv_bfloat16 sA[2][GBM * ASTR];
    __shared__ alignas(16) __nv_bfloat16 sB[2][GBN * ASTR];

    const int tid = threadIdx.x;
    const int lane = tid & 31;
    const int w = tid >> 5;
    const int m0 = blockIdx.y * GBM;
    const int n0 = blockIdx.x * GBN;
    const int wm = (w >> 2) * 64;   // warp m-offset within tile
    const int wn = (w & 3) * 32;    // warp n-offset

    const uint32_t sAu = (uint32_t)__cvta_generic_to_shared(&sA[0][0]);
    const uint32_t sBu = (uint32_t)__cvta_generic_to_shared(&sB[0][0]);
    const uint32_t bufA = GBM * ASTR * 2;  // bytes per A buffer
    const uint32_t bufB = GBN * ASTR * 2;

    // fragment addressing (per-thread invariants)
    const int a_row = wm + (lane & 15);
    const int a_col = (lane >> 4) * 8;
    const int b_row = wn + ((lane >> 4) & 1) * 8 + (lane & 7);
    const int b_col = ((lane >> 3) & 1) * 8;

    float acc[4][4][4];
#pragma unroll
    for (int i = 0; i < 4; ++i)
#pragma unroll
        for (int j = 0; j < 4; ++j)
#pragma unroll
            for (int r = 0; r < 4; ++r) acc[i][j][r] = 0.0f;

    auto load_tiles = [&](int buf, int k0) {
#pragma unroll
        for (int s = 0; s < 2; ++s) {
            int c = tid + s * 256;          // 512 16B-chunks per matrix
            int row = c >> 2;
            int ko = (c & 3) * 8;           // bf16 elems
            cp16(sAu + buf * bufA + (row * ASTR + ko) * 2,
                 A + (size_t)(m0 + row) * K + k0 + ko);
            cp16(sBu + buf * bufB + (row * ASTR + ko) * 2,
                 W + (size_t)(n0 + row) * K + k0 + ko);
        }
        asm volatile("cp.async.commit_group;\n");
    };

    const int iters = K / GBK;
    load_tiles(0, 0);

    for (int it = 0; it < iters; ++it) {
        if (it + 1 < iters) {
            load_tiles((it + 1) & 1, (it + 1) * GBK);
            asm volatile("cp.async.wait_group 1;\n");
        } else {
            asm volatile("cp.async.wait_group 0;\n");
        }
        __syncthreads();

        const int buf = it & 1;
#pragma unroll
        for (int ks = 0; ks < GBK; ks += 16) {
            uint32_t af[4][4];
#pragma unroll
            for (int mi = 0; mi < 4; ++mi) {
                uint32_t addr = sAu + buf * bufA +
                    ((a_row + mi * 16) * ASTR + ks + a_col) * 2;
                asm volatile(
                    "ldmatrix.sync.aligned.m8n8.x4.shared.b16 {%0,%1,%2,%3},[%4];\n"
                    : "=r"(af[mi][0]), "=r"(af[mi][1]), "=r"(af[mi][2]), "=r"(af[mi][3])
                    : "r"(addr));
            }
            uint32_t bf[4][2];
#pragma unroll
            for (int np = 0; np < 2; ++np) {
                uint32_t addr = sBu + buf * bufB +
                    ((b_row + np * 16) * ASTR + ks + b_col) * 2;
                uint32_t r0, r1, r2, r3;
                asm volatile(
                    "ldmatrix.sync.aligned.m8n8.x4.shared.b16 {%0,%1,%2,%3},[%4];\n"
                    : "=r"(r0), "=r"(r1), "=r"(r2), "=r"(r3) : "r"(addr));
                bf[np * 2][0] = r0; bf[np * 2][1] = r1;
                bf[np * 2 + 1][0] = r2; bf[np * 2 + 1][1] = r3;
            }
#pragma unroll
            for (int mi = 0; mi < 4; ++mi)
#pragma unroll
                for (int ni = 0; ni < 4; ++ni) {
                    asm volatile(
                        "mma.sync.aligned.m16n8k16.row.col.f32.bf16.bf16.f32 "
                        "{%0,%1,%2,%3},{%4,%5,%6,%7},{%8,%9},{%0,%1,%2,%3};\n"
                        : "+f"(acc[mi][ni][0]), "+f"(acc[mi][ni][1]),
                          "+f"(acc[mi][ni][2]), "+f"(acc[mi][ni][3])
                        : "r"(af[mi][0]), "r"(af[mi][1]), "r"(af[mi][2]), "r"(af[mi][3]),
                          "r"(bf[ni][0]), "r"(bf[ni][1]));
                }
        }
        __syncthreads();
    }

    // epilogue: c-frag rows g / g+8, cols 2*(lane&3), 2*(lane&3)+1
    const int g = lane >> 2;
    const int cc = (lane & 3) * 2;
#pragma unroll
    for (int mi = 0; mi < 4; ++mi) {
#pragma unroll
        for (int ni = 0; ni < 4; ++ni) {
            int row = m0 + wm + mi * 16 + g;
            int col = n0 + wn + ni * 8 + cc;
            *(float2*)(C + (size_t)row * Nn + col) =
                make_float2(acc[mi][ni][0], acc[mi][ni][1]);
            *(float2*)(C + (size_t)(row + 8) * Nn + col) =
                make_float2(acc[mi][ni][2], acc[mi][ni][3]);
        }
    }
}

// ---------------------------------------------------------------------------
// Column partial sums of g_HF per batch (for the sequence mean)
// ---------------------------------------------------------------------------
__global__ void colmean_kernel()
{
    int c = blockIdx.x * 128 + threadIdx.x;
    int b = blockIdx.y;
    int r = blockIdx.z;
    const float* base = g_HF + (size_t)(b * NSEQ + r * 256) * DMODEL + c;
    float s = 0.0f;
#pragma unroll 4
    for (int row = 0; row < 256; ++row)
        s += base[(size_t)row * DMODEL];
    g_partial[r][b][c] = s;
}

// ---------------------------------------------------------------------------
// cvec[b][h][j] = sum_e (W1[h,j,64+e] + W1[h,j,128+e]) * mean[b][h*64+e] + b1[h,j]
// ---------------------------------------------------------------------------
__global__ void cvec_kernel(const float* __restrict__ fuW1,
                            const float* __restrict__ fub1)
{
    __shared__ float mn[HD];
    int h = blockIdx.x, b = blockIdx.y, j = threadIdx.x;
    int c = h * HD + j;
    mn[j] = (g_partial[0][b][c] + g_partial[1][b][c] +
             g_partial[2][b][c] + g_partial[3][b][c]) * (1.0f / 1024.0f);
    __syncthreads();
    const float* wrow = fuW1 + (size_t)(h * HD + j) * (3 * HD);
    float acc = fub1[h * HD + j];
#pragma unroll
    for (int e = 0; e < HD; ++e)
        acc = fmaf(wrow[64 + e] + wrow[128 + e], mn[e], acc);
    g_cvec[b][h][j] = acc;
}

// ---------------------------------------------------------------------------
// Fusion MLP: per (64-token tile, head): two 64x64x64 GEMMs with exact GELU.
// 4x4 register tile per thread; both operands via LDS128.
// Writes multi directly in split-precision extended-K layout.
// ---------------------------------------------------------------------------
__device__ __forceinline__ float gelu_exact(float x) {
    return 0.5f * x * (1.0f + erff(x * 0.70710678118654752f));
}

__global__ __launch_bounds__(256) void fusion_kernel(
    const float* __restrict__ fuW1, const float* __restrict__ fuW2,
    const float* __restrict__ fub2)
{
    __shared__ float aT[HD][68];   // [e][t] hf transposed; later [j][t] gelu out
    __shared__ float bT[HD][68];   // [e][j] W1a; later [j][f] W2

    const int tid = threadIdx.x;
    const int m0 = blockIdx.x * 64;
    const int h = blockIdx.y;
    const int b = m0 >> 10;
    const int tr = tid >> 4;   // 0..15 -> tokens 4tr..4tr+3
    const int tc = tid & 15;   // 0..15 -> cols 4tc..4tc+3

    for (int idx = tid; idx < 64 * 64; idx += 256) {
        int t = idx >> 6, e = idx & 63;
        aT[e][t] = g_HF[(size_t)(m0 + t) * DMODEL + h * HD + e];
    }
    for (int idx = tid; idx < 64 * 64; idx += 256) {
        int j = idx >> 6, e = idx & 63;
        bT[e][j] = fuW1[(size_t)(h * HD + j) * (3 * HD) + e];
    }
    __syncthreads();

    float acc[4][4];
#pragma unroll
    for (int i = 0; i < 4; ++i)
#pragma unroll
        for (int j = 0; j < 4; ++j) acc[i][j] = 0.0f;

#pragma unroll
    for (int e = 0; e < HD; ++e) {
        float4 a = *(const float4*)&aT[e][tr * 4];
        float4 bv = *(const float4*)&bT[e][tc * 4];
        float ra[4] = {a.x, a.y, a.z, a.w};
        float rb[4] = {bv.x, bv.y, bv.z, bv.w};
#pragma unroll
        for (int i = 0; i < 4; ++i)
#pragma unroll
            for (int j = 0; j < 4; ++j)
                acc[i][j] = fmaf(ra[i], rb[j], acc[i][j]);
    }
    __syncthreads();   // all reads of aT/bT done

    // gelu -> aT[j][t]; load W2 -> bT[j][f]
#pragma unroll
    for (int jj = 0; jj < 4; ++jj) {
        int j = tc * 4 + jj;
        float cv = g_cvec[b][h][j];
        float4 gv;
        gv.x = gelu_exact(acc[0][jj] + cv);
        gv.y = gelu_exact(acc[1][jj] + cv);
        gv.z = gelu_exact(acc[2][jj] + cv);
        gv.w = gelu_exact(acc[3][jj] + cv);
        *(float4*)&aT[j][tr * 4] = gv;
    }
    for (int idx = tid; idx < 64 * 64; idx += 256) {
        int f = idx >> 6, j = idx & 63;
        bT[j][f] = fuW2[(size_t)(h * HD + f) * HD + j];
    }
    __syncthreads();

    float acc2[4][4];
#pragma unroll
    for (int i = 0; i < 4; ++i)
#pragma unroll
        for (int j = 0; j < 4; ++j) acc2[i][j] = 0.0f;

#pragma unroll
    for (int j = 0; j < HD; ++j) {
        float4 a = *(const float4*)&aT[j][tr * 4];
        float4 bv = *(const float4*)&bT[j][tc * 4];
        float ra[4] = {a.x, a.y, a.z, a.w};
        float rb[4] = {bv.x, bv.y, bv.z, bv.w};
#pragma unroll
        for (int i = 0; i < 4; ++i)
#pragma unroll
            for (int jj = 0; jj < 4; ++jj)
                acc2[i][jj] = fmaf(ra[i], rb[jj], acc2[i][jj]);
    }

    float bias[4];
#pragma unroll
    for (int jj = 0; jj < 4; ++jj) bias[jj] = fub2[h * HD + tc * 4 + jj];

#pragma unroll
    for (int i = 0; i < 4; ++i) {
        int t = tr * 4 + i;
        float x0 = acc2[i][0] + bias[0];
        float x1 = acc2[i][1] + bias[1];
        float x2 = acc2[i][2] + bias[2];
        float x3 = acc2[i][3] + bias[3];
        __nv_bfloat16 h0 = __float2bfloat16_rn(x0);
        __nv_bfloat16 h1 = __float2bfloat16_rn(x1);
        __nv_bfloat16 h2 = __float2bfloat16_rn(x2);
        __nv_bfloat16 h3 = __float2bfloat16_rn(x3);
        __nv_bfloat162 hA = {h0, h1}, hB = {h2, h3};
        __nv_bfloat162 lA = {__float2bfloat16_rn(x0 - __bfloat162float(h0)),
                             __float2bfloat16_rn(x1 - __bfloat162float(h1))};
        __nv_bfloat162 lB = {__float2bfloat16_rn(x2 - __bfloat162float(h2)),
                             __float2bfloat16_rn(x3 - __bfloat162float(h3))};
        size_t base = (size_t)(m0 + t) * K3 + h * HD + tc * 4;
        // A-layout: hi at [0,K), lo at [K,2K), hi at [2K,3K)
        *(__nv_bfloat162*)&g_multiS[base]                  = hA;
        *(__nv_bfloat162*)&g_multiS[base + 2]              = hB;
        *(__nv_bfloat162*)&g_multiS[base + DMODEL]         = lA;
        *(__nv_bfloat162*)&g_multiS[base + DMODEL + 2]     = lB;
        *(__nv_bfloat162*)&g_multiS[base + 2 * DMODEL]     = hA;
        *(__nv_bfloat162*)&g_multiS[base + 2 * DMODEL + 2] = hB;
    }
}

// ---------------------------------------------------------------------------
// Trivial outputs: fwd/bwd targets + avg_strength (analytic constants)
// ---------------------------------------------------------------------------
__global__ void extras_kernel(const int* __restrict__ prev,
                              const float* __restrict__ cr,
                              float* __restrict__ out)
{
    int idx = blockIdx.x * blockDim.x + threadIdx.x;
    if (idx >= NTOK) return;
    int n = idx & (NSEQ - 1);

    float thr = floorf((float)NSEQ / (1.0f + expf(-cr[0])));
    float fwd = 511.0f;
    if ((float)n >= thr) {
        int p = prev[idx];
        p = p < 0 ? 0 : (p > NSEQ - 1 ? NSEQ - 1 : p);
        fwd = (float)p;
    }
    out[OFF_FWD + idx] = fwd;
    out[OFF_BWD + idx] = 511.0f;
    out[OFF_STR + idx] = 1.0f - logf(1.0f / (float)NSEQ + 1e-8f);
}

// ---------------------------------------------------------------------------
extern "C" void kernel_launch(void* const* d_in, const int* in_sizes, int n_in,
                              void* d_out, int out_size)
{
    const float* h    = (const float*)d_in[0];
    const int*   prev = (const int*)d_in[1];
    // d_in[2..9]: forward/backward encoder weights — provably dead code
    const float* Wv   = (const float*)d_in[10];
    const float* fuW1 = (const float*)d_in[11];
    const float* fub1 = (const float*)d_in[12];
    const float* fuW2 = (const float*)d_in[13];
    const float* fub2 = (const float*)d_in[14];
    const float* Wo   = (const float*)d_in[15];
    const float* cr   = (const float*)d_in[16];
    float* out = (float*)d_out;

    float *pHF = nullptr;
    __nv_bfloat16 *phS = nullptr, *pWvS = nullptr, *pWoS = nullptr, *pMS = nullptr;
    cudaGetSymbolAddress((void**)&pHF, g_HF);
    cudaGetSymbolAddress((void**)&phS, g_hS);
    cudaGetSymbolAddress((void**)&pWvS, g_WvS);
    cudaGetSymbolAddress((void**)&pWoS, g_WoS);
    cudaGetSymbolAddress((void**)&pMS, g_multiS);

    // 0) split-precision converts (A-layout for h; B-layout for weights)
    split3_kernel<<<(NTOK * DMODEL / 4 + 255) / 256, 256>>>(
        h, phS, NTOK * DMODEL, DMODEL, 2 * DMODEL);
    split3_kernel<<<(DMODEL * DMODEL / 4 + 255) / 256, 256>>>(
        Wv, pWvS, DMODEL * DMODEL, 2 * DMODEL, DMODEL);
    split3_kernel<<<(DMODEL * DMODEL / 4 + 255) / 256, 256>>>(
        Wo, pWoS, DMODEL * DMODEL, 2 * DMODEL, DMODEL);

    dim3 g1(DMODEL / GBN, NTOK / GBM);

    // 1) head_features = h @ Wv^T  (split bf16: hi*hi + lo*hi + hi*lo)
    gemm_bf16_nt<<<g1, 256>>>(phS, pWvS, pHF, NTOK, DMODEL, K3);

    // 2) sequence-mean partials per batch
    colmean_kernel<<<dim3(DMODEL / 128, NB, 4), 128>>>();

    // 3) constant part of fusion stage-1
    cvec_kernel<<<dim3(NH, NB), HD>>>(fuW1, fub1);

    // 4) fusion MLP -> g_multiS (split layout)
    fusion_kernel<<<dim3(NTOK / 64, NH), 256>>>(fuW1, fuW2, fub2);

    // 5) final_output = multi @ Wo^T
    gemm_bf16_nt<<<g1, 256>>>(pMS, pWoS, out, NTOK, DMODEL, K3);

    // 6) analytic outputs
    extras_kernel<<<(NTOK + 255) / 256, 256>>>(prev, cr, out);
}

// round 6
// speedup vs baseline: 1.8887x; 1.0457x over previous
#include <cuda_runtime.h>
#include <cuda_bf16.h>
#include <math.h>
#include <stdint.h>

#define NTOK 2048   // B*N
#define DMODEL 1024
#define NSEQ 1024
#define NB 2
#define NH 16
#define HD 64
#define K3 (3 * DMODEL)   // extended split-precision K

// Output layout (float32, concatenated in reference return order)
#define OFF_FIN 0
#define OFF_FWD 2097152
#define OFF_BWD 2099200
#define OFF_STR 2101248

// scratch (device globals — no runtime allocation allowed)
__device__ float g_HF[NTOK * DMODEL];                      // head_features fp32
__device__ float g_partial[4][NB][DMODEL];                 // column-sum partials
__device__ float g_cvec[NB][NH][HD];                       // W1_mid_sum @ mean + b1
// split-precision bf16 operands, extended-K layout (rows of length 3*DMODEL)
__device__ alignas(16) __nv_bfloat16 g_hS[NTOK * K3];      // h:  [hi | lo | hi]
__device__ alignas(16) __nv_bfloat16 g_WvS[DMODEL * K3];   // Wv: [hi | hi | lo]
__device__ alignas(16) __nv_bfloat16 g_WoS[DMODEL * K3];   // Wo: [hi | hi | lo]
__device__ alignas(16) __nv_bfloat16 g_multiS[NTOK * K3];  // multi: [hi | lo | hi]

// ---------------------------------------------------------------------------
// fp32 -> split bf16 (hi at k and o_hi2, lo at o_lo) in extended-K rows
// ---------------------------------------------------------------------------
__global__ void split3_kernel(const float* __restrict__ in,
                              __nv_bfloat16* __restrict__ out,
                              int n, int o_lo, int o_hi2)
{
    int i = (blockIdx.x * blockDim.x + threadIdx.x) * 4;
    if (i >= n) return;
    int row = i >> 10;           // K = DMODEL = 1024 per row
    int k = i & 1023;
    float4 v = *(const float4*)(in + i);

    __nv_bfloat16 h0 = __float2bfloat16_rn(v.x);
    __nv_bfloat16 h1 = __float2bfloat16_rn(v.y);
    __nv_bfloat16 h2 = __float2bfloat16_rn(v.z);
    __nv_bfloat16 h3 = __float2bfloat16_rn(v.w);
    __nv_bfloat16 l0 = __float2bfloat16_rn(v.x - __bfloat162float(h0));
    __nv_bfloat16 l1 = __float2bfloat16_rn(v.y - __bfloat162float(h1));
    __nv_bfloat16 l2 = __float2bfloat16_rn(v.z - __bfloat162float(h2));
    __nv_bfloat16 l3 = __float2bfloat16_rn(v.w - __bfloat162float(h3));

    size_t base = (size_t)row * K3 + k;
    __nv_bfloat162 hA = {h0, h1}, hB = {h2, h3};
    __nv_bfloat162 lA = {l0, l1}, lB = {l2, l3};
    *(__nv_bfloat162*)(out + base)              = hA;
    *(__nv_bfloat162*)(out + base + 2)          = hB;
    *(__nv_bfloat162*)(out + base + o_hi2)      = hA;
    *(__nv_bfloat162*)(out + base + o_hi2 + 2)  = hB;
    *(__nv_bfloat162*)(out + base + o_lo)       = lA;
    *(__nv_bfloat162*)(out + base + o_lo + 2)   = lB;
}

// ---------------------------------------------------------------------------
// bf16 tensor-core NT GEMM: C[m][n] = sum_k A[m][k] * W[n][k], fp32 accum/out.
// v2: 128x64 tiles (grid 256 -> 2 CTAs/SM), warp tile 32x32 (8 warps 4x2),
// 3-stage cp.async pipeline, ONE __syncthreads per K-tile.
// smem row stride 40 bf16 (80B) -> ldmatrix conflict-free (5i mod 8 distinct).
// ---------------------------------------------------------------------------
#define GBM 128
#define GBN 64
#define GBK 32
#define STAGES 3
#define ASTR 40  // bf16 elems per smem row

__device__ __forceinline__ void cp16(uint32_t s, const void* g) {
    asm volatile("cp.async.cg.shared.global [%0], [%1], 16;\n" :: "r"(s), "l"(g));
}

__global__ __launch_bounds__(256, 2) void gemm_bf16_nt(
    const __nv_bfloat16* __restrict__ A, const __nv_bfloat16* __restrict__ W,
    float* __restrict__ C, int M, int Nn, int K)
{
    __shared__ alignas(16) __nv_bfloat16 sA[STAGES][GBM * ASTR];  // 10240 B/stage
    __shared__ alignas(16) __nv_bfloat16 sB[STAGES][GBN * ASTR];  //  5120 B/stage

    const int tid = threadIdx.x;
    const int lane = tid & 31;
    const int w = tid >> 5;
    const int m0 = blockIdx.y * GBM;
    const int n0 = blockIdx.x * GBN;
    const int wm = (w >> 1) * 32;   // 4 warp rows
    const int wn = (w & 1) * 32;    // 2 warp cols

    const uint32_t sAu = (uint32_t)__cvta_generic_to_shared(&sA[0][0]);
    const uint32_t sBu = (uint32_t)__cvta_generic_to_shared(&sB[0][0]);
    const uint32_t bufA = GBM * ASTR * 2;  // bytes per A stage
    const uint32_t bufB = GBN * ASTR * 2;

    // fragment addressing (per-thread invariants)
    const int a_row = wm + (lane & 15);
    const int a_col = (lane >> 4) * 8;
    const int b_row = wn + ((lane >> 4) & 1) * 8 + (lane & 7);
    const int b_col = ((lane >> 3) & 1) * 8;

    float acc[2][4][4];
#pragma unroll
    for (int i = 0; i < 2; ++i)
#pragma unroll
        for (int j = 0; j < 4; ++j)
#pragma unroll
            for (int r = 0; r < 4; ++r) acc[i][j][r] = 0.0f;

    auto load_tiles = [&](int stg, int k0) {
        uint32_t aoff = sAu + stg * bufA;
        uint32_t boff = sBu + stg * bufB;
#pragma unroll
        for (int s = 0; s < 2; ++s) {
            int c = tid + s * 256;          // 512 16B-chunks for A
            int row = c >> 2;
            int ko = (c & 3) * 8;
            cp16(aoff + (row * ASTR + ko) * 2,
                 A + (size_t)(m0 + row) * K + k0 + ko);
        }
        {
            int row = tid >> 2;             // 256 16B-chunks for B
            int ko = (tid & 3) * 8;
            cp16(boff + (row * ASTR + ko) * 2,
                 W + (size_t)(n0 + row) * K + k0 + ko);
        }
        asm volatile("cp.async.commit_group;\n");
    };

    const int iters = K / GBK;
    load_tiles(0, 0);
    load_tiles(1, GBK);

    for (int it = 0; it < iters; ++it) {
        if (it < iters - 1) {
            asm volatile("cp.async.wait_group 1;\n");
        } else {
            asm volatile("cp.async.wait_group 0;\n");
        }
        __syncthreads();

        // prefetch stage it+2 (its buffer was consumed at iter it-1; the
        // barrier above ordered all of that compute before these writes)
        if (it + 2 < iters) load_tiles((it + 2) % STAGES, (it + 2) * GBK);

        const int buf = it % STAGES;
        const uint32_t aoff = sAu + buf * bufA;
        const uint32_t boff = sBu + buf * bufB;
#pragma unroll
        for (int ks = 0; ks < GBK; ks += 16) {
            uint32_t af[2][4];
#pragma unroll
            for (int mi = 0; mi < 2; ++mi) {
                uint32_t addr = aoff + ((a_row + mi * 16) * ASTR + ks + a_col) * 2;
                asm volatile(
                    "ldmatrix.sync.aligned.m8n8.x4.shared.b16 {%0,%1,%2,%3},[%4];\n"
                    : "=r"(af[mi][0]), "=r"(af[mi][1]), "=r"(af[mi][2]), "=r"(af[mi][3])
                    : "r"(addr));
            }
            uint32_t bf[4][2];
#pragma unroll
            for (int np = 0; np < 2; ++np) {
                uint32_t addr = boff + ((b_row + np * 16) * ASTR + ks + b_col) * 2;
                uint32_t r0, r1, r2, r3;
                asm volatile(
                    "ldmatrix.sync.aligned.m8n8.x4.shared.b16 {%0,%1,%2,%3},[%4];\n"
                    : "=r"(r0), "=r"(r1), "=r"(r2), "=r"(r3) : "r"(addr));
                bf[np * 2][0] = r0; bf[np * 2][1] = r1;
                bf[np * 2 + 1][0] = r2; bf[np * 2 + 1][1] = r3;
            }
#pragma unroll
            for (int mi = 0; mi < 2; ++mi)
#pragma unroll
                for (int ni = 0; ni < 4; ++ni) {
                    asm volatile(
                        "mma.sync.aligned.m16n8k16.row.col.f32.bf16.bf16.f32 "
                        "{%0,%1,%2,%3},{%4,%5,%6,%7},{%8,%9},{%0,%1,%2,%3};\n"
                        : "+f"(acc[mi][ni][0]), "+f"(acc[mi][ni][1]),
                          "+f"(acc[mi][ni][2]), "+f"(acc[mi][ni][3])
                        : "r"(af[mi][0]), "r"(af[mi][1]), "r"(af[mi][2]), "r"(af[mi][3]),
                          "r"(bf[ni][0]), "r"(bf[ni][1]));
                }
        }
    }

    // epilogue: c-frag rows g / g+8, cols 2*(lane&3), 2*(lane&3)+1
    const int g = lane >> 2;
    const int cc = (lane & 3) * 2;
#pragma unroll
    for (int mi = 0; mi < 2; ++mi) {
#pragma unroll
        for (int ni = 0; ni < 4; ++ni) {
            int row = m0 + wm + mi * 16 + g;
            int col = n0 + wn + ni * 8 + cc;
            *(float2*)(C + (size_t)row * Nn + col) =
                make_float2(acc[mi][ni][0], acc[mi][ni][1]);
            *(float2*)(C + (size_t)(row + 8) * Nn + col) =
                make_float2(acc[mi][ni][2], acc[mi][ni][3]);
        }
    }
}

// ---------------------------------------------------------------------------
// Column partial sums of g_HF per batch (for the sequence mean)
// ---------------------------------------------------------------------------
__global__ void colmean_kernel()
{
    int c = blockIdx.x * 128 + threadIdx.x;
    int b = blockIdx.y;
    int r = blockIdx.z;
    const float* base = g_HF + (size_t)(b * NSEQ + r * 256) * DMODEL + c;
    float s = 0.0f;
#pragma unroll 4
    for (int row = 0; row < 256; ++row)
        s += base[(size_t)row * DMODEL];
    g_partial[r][b][c] = s;
}

// ---------------------------------------------------------------------------
// cvec[b][h][j] = sum_e (W1[h,j,64+e] + W1[h,j,128+e]) * mean[b][h*64+e] + b1[h,j]
// ---------------------------------------------------------------------------
__global__ void cvec_kernel(const float* __restrict__ fuW1,
                            const float* __restrict__ fub1)
{
    __shared__ float mn[HD];
    int h = blockIdx.x, b = blockIdx.y, j = threadIdx.x;
    int c = h * HD + j;
    mn[j] = (g_partial[0][b][c] + g_partial[1][b][c] +
             g_partial[2][b][c] + g_partial[3][b][c]) * (1.0f / 1024.0f);
    __syncthreads();
    const float* wrow = fuW1 + (size_t)(h * HD + j) * (3 * HD);
    float acc = fub1[h * HD + j];
#pragma unroll
    for (int e = 0; e < HD; ++e)
        acc = fmaf(wrow[64 + e] + wrow[128 + e], mn[e], acc);
    g_cvec[b][h][j] = acc;
}

// ---------------------------------------------------------------------------
// Fusion MLP: per (64-token tile, head): two 64x64x64 GEMMs with exact GELU.
// 4x4 register tile per thread; both operands via LDS128.
// Writes multi directly in split-precision extended-K layout.
// ---------------------------------------------------------------------------
__device__ __forceinline__ float gelu_exact(float x) {
    return 0.5f * x * (1.0f + erff(x * 0.70710678118654752f));
}

__global__ __launch_bounds__(256) void fusion_kernel(
    const float* __restrict__ fuW1, const float* __restrict__ fuW2,
    const float* __restrict__ fub2)
{
    __shared__ float aT[HD][68];   // [e][t] hf transposed; later [j][t] gelu out
    __shared__ float bT[HD][68];   // [e][j] W1a; later [j][f] W2

    const int tid = threadIdx.x;
    const int m0 = blockIdx.x * 64;
    const int h = blockIdx.y;
    const int b = m0 >> 10;
    const int tr = tid >> 4;   // 0..15 -> tokens 4tr..4tr+3
    const int tc = tid & 15;   // 0..15 -> cols 4tc..4tc+3

    for (int idx = tid; idx < 64 * 64; idx += 256) {
        int t = idx >> 6, e = idx & 63;
        aT[e][t] = g_HF[(size_t)(m0 + t) * DMODEL + h * HD + e];
    }
    for (int idx = tid; idx < 64 * 64; idx += 256) {
        int j = idx >> 6, e = idx & 63;
        bT[e][j] = fuW1[(size_t)(h * HD + j) * (3 * HD) + e];
    }
    __syncthreads();

    float acc[4][4];
#pragma unroll
    for (int i = 0; i < 4; ++i)
#pragma unroll
        for (int j = 0; j < 4; ++j) acc[i][j] = 0.0f;

#pragma unroll
    for (int e = 0; e < HD; ++e) {
        float4 a = *(const float4*)&aT[e][tr * 4];
        float4 bv = *(const float4*)&bT[e][tc * 4];
        float ra[4] = {a.x, a.y, a.z, a.w};
        float rb[4] = {bv.x, bv.y, bv.z, bv.w};
#pragma unroll
        for (int i = 0; i < 4; ++i)
#pragma unroll
            for (int j = 0; j < 4; ++j)
                acc[i][j] = fmaf(ra[i], rb[j], acc[i][j]);
    }
    __syncthreads();   // all reads of aT/bT done

    // gelu -> aT[j][t]; load W2 -> bT[j][f]
#pragma unroll
    for (int jj = 0; jj < 4; ++jj) {
        int j = tc * 4 + jj;
        float cv = g_cvec[b][h][j];
        float4 gv;
        gv.x = gelu_exact(acc[0][jj] + cv);
        gv.y = gelu_exact(acc[1][jj] + cv);
        gv.z = gelu_exact(acc[2][jj] + cv);
        gv.w = gelu_exact(acc[3][jj] + cv);
        *(float4*)&aT[j][tr * 4] = gv;
    }
    for (int idx = tid; idx < 64 * 64; idx += 256) {
        int f = idx >> 6, j = idx & 63;
        bT[j][f] = fuW2[(size_t)(h * HD + f) * HD + j];
    }
    __syncthreads();

    float acc2[4][4];
#pragma unroll
    for (int i = 0; i < 4; ++i)
#pragma unroll
        for (int j = 0; j < 4; ++j) acc2[i][j] = 0.0f;

#pragma unroll
    for (int j = 0; j < HD; ++j) {
        float4 a = *(const float4*)&aT[j][tr * 4];
        float4 bv = *(const float4*)&bT[j][tc * 4];
        float ra[4] = {a.x, a.y, a.z, a.w};
        float rb[4] = {bv.x, bv.y, bv.z, bv.w};
#pragma unroll
        for (int i = 0; i < 4; ++i)
#pragma unroll
            for (int jj = 0; jj < 4; ++jj)
                acc2[i][jj] = fmaf(ra[i], rb[jj], acc2[i][jj]);
    }

    float bias[4];
#pragma unroll
    for (int jj = 0; jj < 4; ++jj) bias[jj] = fub2[h * HD + tc * 4 + jj];

#pragma unroll
    for (int i = 0; i < 4; ++i) {
        int t = tr * 4 + i;
        float x0 = acc2[i][0] + bias[0];
        float x1 = acc2[i][1] + bias[1];
        float x2 = acc2[i][2] + bias[2];
        float x3 = acc2[i][3] + bias[3];
        __nv_bfloat16 h0 = __float2bfloat16_rn(x0);
        __nv_bfloat16 h1 = __float2bfloat16_rn(x1);
        __nv_bfloat16 h2 = __float2bfloat16_rn(x2);
        __nv_bfloat16 h3 = __float2bfloat16_rn(x3);
        __nv_bfloat162 hA = {h0, h1}, hB = {h2, h3};
        __nv_bfloat162 lA = {__float2bfloat16_rn(x0 - __bfloat162float(h0)),
                             __float2bfloat16_rn(x1 - __bfloat162float(h1))};
        __nv_bfloat162 lB = {__float2bfloat16_rn(x2 - __bfloat162float(h2)),
                             __float2bfloat16_rn(x3 - __bfloat162float(h3))};
        size_t base = (size_t)(m0 + t) * K3 + h * HD + tc * 4;
        // A-layout: hi at [0,K), lo at [K,2K), hi at [2K,3K)
        *(__nv_bfloat162*)&g_multiS[base]                  = hA;
        *(__nv_bfloat162*)&g_multiS[base + 2]              = hB;
        *(__nv_bfloat162*)&g_multiS[base + DMODEL]         = lA;
        *(__nv_bfloat162*)&g_multiS[base + DMODEL + 2]     = lB;
        *(__nv_bfloat162*)&g_multiS[base + 2 * DMODEL]     = hA;
        *(__nv_bfloat162*)&g_multiS[base + 2 * DMODEL + 2] = hB;
    }
}

// ---------------------------------------------------------------------------
// Trivial outputs: fwd/bwd targets + avg_strength (analytic constants)
// ---------------------------------------------------------------------------
__global__ void extras_kernel(const int* __restrict__ prev,
                              const float* __restrict__ cr,
                              float* __restrict__ out)
{
    int idx = blockIdx.x * blockDim.x + threadIdx.x;
    if (idx >= NTOK) return;
    int n = idx & (NSEQ - 1);

    float thr = floorf((float)NSEQ / (1.0f + expf(-cr[0])));
    float fwd = 511.0f;
    if ((float)n >= thr) {
        int p = prev[idx];
        p = p < 0 ? 0 : (p > NSEQ - 1 ? NSEQ - 1 : p);
        fwd = (float)p;
    }
    out[OFF_FWD + idx] = fwd;
    out[OFF_BWD + idx] = 511.0f;
    out[OFF_STR + idx] = 1.0f - logf(1.0f / (float)NSEQ + 1e-8f);
}

// ---------------------------------------------------------------------------
extern "C" void kernel_launch(void* const* d_in, const int* in_sizes, int n_in,
                              void* d_out, int out_size)
{
    const float* h    = (const float*)d_in[0];
    const int*   prev = (const int*)d_in[1];
    // d_in[2..9]: forward/backward encoder weights — provably dead code
    const float* Wv   = (const float*)d_in[10];
    const float* fuW1 = (const float*)d_in[11];
    const float* fub1 = (const float*)d_in[12];
    const float* fuW2 = (const float*)d_in[13];
    const float* fub2 = (const float*)d_in[14];
    const float* Wo   = (const float*)d_in[15];
    const float* cr   = (const float*)d_in[16];
    float* out = (float*)d_out;

    float *pHF = nullptr;
    __nv_bfloat16 *phS = nullptr, *pWvS = nullptr, *pWoS = nullptr, *pMS = nullptr;
    cudaGetSymbolAddress((void**)&pHF, g_HF);
    cudaGetSymbolAddress((void**)&phS, g_hS);
    cudaGetSymbolAddress((void**)&pWvS, g_WvS);
    cudaGetSymbolAddress((void**)&pWoS, g_WoS);
    cudaGetSymbolAddress((void**)&pMS, g_multiS);

    // 0) split-precision converts (A-layout for h; B-layout for weights)
    split3_kernel<<<(NTOK * DMODEL / 4 + 255) / 256, 256>>>(
        h, phS, NTOK * DMODEL, DMODEL, 2 * DMODEL);
    split3_kernel<<<(DMODEL * DMODEL / 4 + 255) / 256, 256>>>(
        Wv, pWvS, DMODEL * DMODEL, 2 * DMODEL, DMODEL);
    split3_kernel<<<(DMODEL * DMODEL / 4 + 255) / 256, 256>>>(
        Wo, pWoS, DMODEL * DMODEL, 2 * DMODEL, DMODEL);

    dim3 g1(DMODEL / GBN, NTOK / GBM);   // (16, 16) = 256 CTAs

    // 1) head_features = h @ Wv^T  (split bf16: hi*hi + lo*hi + hi*lo)
    gemm_bf16_nt<<<g1, 256>>>(phS, pWvS, pHF, NTOK, DMODEL, K3);

    // 2) sequence-mean partials per batch
    colmean_kernel<<<dim3(DMODEL / 128, NB, 4), 128>>>();

    // 3) constant part of fusion stage-1
    cvec_kernel<<<dim3(NH, NB), HD>>>(fuW1, fub1);

    // 4) fusion MLP -> g_multiS (split layout)
    fusion_kernel<<<dim3(NTOK / 64, NH), 256>>>(fuW1, fuW2, fub2);

    // 5) final_output = multi @ Wo^T
    gemm_bf16_nt<<<g1, 256>>>(pMS, pWoS, out, NTOK, DMODEL, K3);

    // 6) analytic outputs
    extras_kernel<<<(NTOK + 255) / 256, 256>>>(prev, cr, out);
}

// round 8
// speedup vs baseline: 2.0297x; 1.0747x over previous
#include <cuda_runtime.h>
#include <cuda_bf16.h>
#include <math.h>
#include <stdint.h>

#define NTOK 2048   // B*N
#define DMODEL 1024
#define NSEQ 1024
#define NB 2
#define NH 16
#define HD 64
#define K3 (3 * DMODEL)   // extended split-precision K

// Output layout (float32, concatenated in reference return order)
#define OFF_FIN 0
#define OFF_FWD 2097152
#define OFF_BWD 2099200
#define OFF_STR 2101248

// scratch (device globals — no runtime allocation allowed)
__device__ float g_HF[NTOK * DMODEL];                      // head_features fp32
__device__ float g_partial[4][NB][DMODEL];                 // column-sum partials
__device__ float g_cvec[NB][NH][HD];                       // W1_mid_sum @ mean + b1
// split-precision bf16 operands, extended-K layout (rows of length 3*DMODEL)
__device__ alignas(16) __nv_bfloat16 g_hS[NTOK * K3];      // h:  [hi | lo | hi]
__device__ alignas(16) __nv_bfloat16 g_WvS[DMODEL * K3];   // Wv: [hi | hi | lo]
__device__ alignas(16) __nv_bfloat16 g_WoS[DMODEL * K3];   // Wo: [hi | hi | lo]
__device__ alignas(16) __nv_bfloat16 g_multiS[NTOK * K3];  // multi: [hi | lo | hi]

// ---------------------------------------------------------------------------
// fp32 -> split bf16 (hi at k and o_hi2, lo at o_lo) in extended-K rows
// ---------------------------------------------------------------------------
__global__ void split3_kernel(const float* __restrict__ in,
                              __nv_bfloat16* __restrict__ out,
                              int n, int o_lo, int o_hi2)
{
    int i = (blockIdx.x * blockDim.x + threadIdx.x) * 4;
    if (i >= n) return;
    int row = i >> 10;           // K = DMODEL = 1024 per row
    int k = i & 1023;
    float4 v = *(const float4*)(in + i);

    __nv_bfloat16 h0 = __float2bfloat16_rn(v.x);
    __nv_bfloat16 h1 = __float2bfloat16_rn(v.y);
    __nv_bfloat16 h2 = __float2bfloat16_rn(v.z);
    __nv_bfloat16 h3 = __float2bfloat16_rn(v.w);
    __nv_bfloat16 l0 = __float2bfloat16_rn(v.x - __bfloat162float(h0));
    __nv_bfloat16 l1 = __float2bfloat16_rn(v.y - __bfloat162float(h1));
    __nv_bfloat16 l2 = __float2bfloat16_rn(v.z - __bfloat162float(h2));
    __nv_bfloat16 l3 = __float2bfloat16_rn(v.w - __bfloat162float(h3));

    size_t base = (size_t)row * K3 + k;
    __nv_bfloat162 hA = {h0, h1}, hB = {h2, h3};
    __nv_bfloat162 lA = {l0, l1}, lB = {l2, l3};
    *(__nv_bfloat162*)(out + base)              = hA;
    *(__nv_bfloat162*)(out + base + 2)          = hB;
    *(__nv_bfloat162*)(out + base + o_hi2)      = hA;
    *(__nv_bfloat162*)(out + base + o_hi2 + 2)  = hB;
    *(__nv_bfloat162*)(out + base + o_lo)       = lA;
    *(__nv_bfloat162*)(out + base + o_lo + 2)   = lB;
}

// ---------------------------------------------------------------------------
// bf16 mma.sync NT GEMM v3: C[m][n] = sum_k A[m][k]*W[n][k], fp32 accum.
// CTA 128x128, 8 warps (2x4), warp tile 64x32. GBK=64, 3-stage cp.async ring,
// ONE __syncthreads per chunk, register double-buffered ldmatrix fragments.
// smem rows padded to 72 elems (144B) -> ldmatrix banks 9i mod 8 distinct.
// ---------------------------------------------------------------------------
#define TILE_M 128
#define TILE_N 128
#define GBK 64
#define NCH (K3 / GBK)       // 48
#define NSTG 3
#define ROWSTR 72                          // bf16 elems per smem row
#define AREG_B (TILE_M * ROWSTR * 2)       // 18432 bytes (A region)
#define STG_BYTES (2 * AREG_B)             // 36864
#define GEMM_SMEM (NSTG * STG_BYTES)       // 110592

__device__ __forceinline__ void cp16(uint32_t s, const void* g) {
    asm volatile("cp.async.cg.shared.global [%0], [%1], 16;\n" :: "r"(s), "l"(g));
}

__global__ __launch_bounds__(256) void gemm_bf16_nt(
    const __nv_bfloat16* __restrict__ A, const __nv_bfloat16* __restrict__ W,
    float* __restrict__ C, int Nn)
{
    extern __shared__ char dsm[];
    const int tid = threadIdx.x;
    const int lane = tid & 31;
    const int w = tid >> 5;
    const int m0 = blockIdx.y * TILE_M;
    const int n0 = blockIdx.x * TILE_N;
    const int wm = (w >> 2) * 64;   // 2 warp rows
    const int wn = (w & 3) * 32;    // 4 warp cols

    const uint32_t sBase = (uint32_t)__cvta_generic_to_shared(dsm);

    // fragment addressing (per-thread invariants)
    const int a_row = wm + (lane & 15);
    const int a_colb = (lane >> 4) * 8;
    const int b_row = wn + ((lane >> 4) & 1) * 8 + (lane & 7);
    const int b_colb = ((lane >> 3) & 1) * 8;

    float acc[4][4][4];
#pragma unroll
    for (int i = 0; i < 4; ++i)
#pragma unroll
        for (int j = 0; j < 4; ++j)
#pragma unroll
            for (int r = 0; r < 4; ++r) acc[i][j][r] = 0.0f;

    auto load_chunk = [&](int ck) {
        int stg = ck % NSTG;
        uint32_t sa = sBase + stg * STG_BYTES;
        uint32_t sb = sa + AREG_B;
        int k0 = ck * GBK;
#pragma unroll
        for (int j = 0; j < 4; ++j) {
            int c = tid + j * 256;        // 1024 16B-chunks each matrix
            int r = c >> 3;               // row 0..127
            int ci = c & 7;               // 16B chunk within 128B row
            uint32_t soff = r * (ROWSTR * 2) + ci * 16;
            cp16(sa + soff, A + (size_t)(m0 + r) * K3 + k0 + ci * 8);
            cp16(sb + soff, W + (size_t)(n0 + r) * K3 + k0 + ci * 8);
        }
        asm volatile("cp.async.commit_group;\n");
    };

    load_chunk(0);
    load_chunk(1);

    for (int it = 0; it < NCH; ++it) {
        if (it < NCH - 1) asm volatile("cp.async.wait_group 1;\n");
        else              asm volatile("cp.async.wait_group 0;\n");
        __syncthreads();
        if (it + 2 < NCH) load_chunk(it + 2);  // overwrites buf consumed at it-1

        const uint32_t sa = sBase + (it % NSTG) * STG_BYTES;
        const uint32_t sb = sa + AREG_B;

        uint32_t af[2][4][4];
        uint32_t bf[2][4][2];

        auto ldfrag = [&](int buf, int ks) {
#pragma unroll
            for (int mi = 0; mi < 4; ++mi) {
                uint32_t addr = sa +
                    ((a_row + mi * 16) * ROWSTR + ks * 16 + a_colb) * 2;
                asm volatile(
                    "ldmatrix.sync.aligned.m8n8.x4.shared.b16 {%0,%1,%2,%3},[%4];\n"
                    : "=r"(af[buf][mi][0]), "=r"(af[buf][mi][1]),
                      "=r"(af[buf][mi][2]), "=r"(af[buf][mi][3])
                    : "r"(addr));
            }
#pragma unroll
            for (int np = 0; np < 2; ++np) {
                uint32_t addr = sb +
                    ((b_row + np * 16) * ROWSTR + ks * 16 + b_colb) * 2;
                uint32_t r0, r1, r2, r3;
                asm volatile(
                    "ldmatrix.sync.aligned.m8n8.x4.shared.b16 {%0,%1,%2,%3},[%4];\n"
                    : "=r"(r0), "=r"(r1), "=r"(r2), "=r"(r3) : "r"(addr));
                bf[buf][np * 2][0] = r0;     bf[buf][np * 2][1] = r1;
                bf[buf][np * 2 + 1][0] = r2; bf[buf][np * 2 + 1][1] = r3;
            }
        };

        ldfrag(0, 0);
#pragma unroll
        for (int ks = 0; ks < 4; ++ks) {
            if (ks < 3) ldfrag((ks + 1) & 1, ks + 1);  // prefetch next k-step
            const int cur = ks & 1;
#pragma unroll
            for (int mi = 0; mi < 4; ++mi)
#pragma unroll
                for (int ni = 0; ni < 4; ++ni) {
                    asm volatile(
                        "mma.sync.aligned.m16n8k16.row.col.f32.bf16.bf16.f32 "
                        "{%0,%1,%2,%3},{%4,%5,%6,%7},{%8,%9},{%0,%1,%2,%3};\n"
                        : "+f"(acc[mi][ni][0]), "+f"(acc[mi][ni][1]),
                          "+f"(acc[mi][ni][2]), "+f"(acc[mi][ni][3])
                        : "r"(af[cur][mi][0]), "r"(af[cur][mi][1]),
                          "r"(af[cur][mi][2]), "r"(af[cur][mi][3]),
                          "r"(bf[cur][ni][0]), "r"(bf[cur][ni][1]));
                }
        }
    }

    // epilogue: c-frag rows g / g+8, cols 2*(lane&3), 2*(lane&3)+1
    const int g = lane >> 2;
    const int cc = (lane & 3) * 2;
#pragma unroll
    for (int mi = 0; mi < 4; ++mi) {
#pragma unroll
        for (int ni = 0; ni < 4; ++ni) {
            int row = m0 + wm + mi * 16 + g;
            int col = n0 + wn + ni * 8 + cc;
            *(float2*)(C + (size_t)row * Nn + col) =
                make_float2(acc[mi][ni][0], acc[mi][ni][1]);
            *(float2*)(C + (size_t)(row + 8) * Nn + col) =
                make_float2(acc[mi][ni][2], acc[mi][ni][3]);
        }
    }
}

// ---------------------------------------------------------------------------
// Column partial sums of g_HF per batch (for the sequence mean)
// ---------------------------------------------------------------------------
__global__ void colmean_kernel()
{
    int c = blockIdx.x * 128 + threadIdx.x;
    int b = blockIdx.y;
    int r = blockIdx.z;
    const float* base = g_HF + (size_t)(b * NSEQ + r * 256) * DMODEL + c;
    float s = 0.0f;
#pragma unroll 4
    for (int row = 0; row < 256; ++row)
        s += base[(size_t)row * DMODEL];
    g_partial[r][b][c] = s;
}

// ---------------------------------------------------------------------------
// cvec[b][h][j] = sum_e (W1[h,j,64+e] + W1[h,j,128+e]) * mean[b][h*64+e] + b1[h,j]
// ---------------------------------------------------------------------------
__global__ void cvec_kernel(const float* __restrict__ fuW1,
                            const float* __restrict__ fub1)
{
    __shared__ float mn[HD];
    int h = blockIdx.x, b = blockIdx.y, j = threadIdx.x;
    int c = h * HD + j;
    mn[j] = (g_partial[0][b][c] + g_partial[1][b][c] +
             g_partial[2][b][c] + g_partial[3][b][c]) * (1.0f / 1024.0f);
    __syncthreads();
    const float* wrow = fuW1 + (size_t)(h * HD + j) * (3 * HD);
    float acc = fub1[h * HD + j];
#pragma unroll
    for (int e = 0; e < HD; ++e)
        acc = fmaf(wrow[64 + e] + wrow[128 + e], mn[e], acc);
    g_cvec[b][h][j] = acc;
}

// ---------------------------------------------------------------------------
// Fusion MLP: per (64-token tile, head): two 64x64x64 GEMMs with exact GELU.
// Writes multi directly in split-precision extended-K layout.
// ---------------------------------------------------------------------------
__device__ __forceinline__ float gelu_exact(float x) {
    return 0.5f * x * (1.0f + erff(x * 0.70710678118654752f));
}

__global__ __launch_bounds__(256) void fusion_kernel(
    const float* __restrict__ fuW1, const float* __restrict__ fuW2,
    const float* __restrict__ fub2)
{
    __shared__ float aT[HD][68];
    __shared__ float bT[HD][68];

    const int tid = threadIdx.x;
    const int m0 = blockIdx.x * 64;
    const int h = blockIdx.y;
    const int b = m0 >> 10;
    const int tr = tid >> 4;
    const int tc = tid & 15;

    for (int idx = tid; idx < 64 * 64; idx += 256) {
        int t = idx >> 6, e = idx & 63;
        aT[e][t] = g_HF[(size_t)(m0 + t) * DMODEL + h * HD + e];
    }
    for (int idx = tid; idx < 64 * 64; idx += 256) {
        int j = idx >> 6, e = idx & 63;
        bT[e][j] = fuW1[(size_t)(h * HD + j) * (3 * HD) + e];
    }
    __syncthreads();

    float acc[4][4];
#pragma unroll
    for (int i = 0; i < 4; ++i)
#pragma unroll
        for (int j = 0; j < 4; ++j) acc[i][j] = 0.0f;

#pragma unroll
    for (int e = 0; e < HD; ++e) {
        float4 a = *(const float4*)&aT[e][tr * 4];
        float4 bv = *(const float4*)&bT[e][tc * 4];
        float ra[4] = {a.x, a.y, a.z, a.w};
        float rb[4] = {bv.x, bv.y, bv.z, bv.w};
#pragma unroll
        for (int i = 0; i < 4; ++i)
#pragma unroll
            for (int j = 0; j < 4; ++j)
                acc[i][j] = fmaf(ra[i], rb[j], acc[i][j]);
    }
    __syncthreads();

#pragma unroll
    for (int jj = 0; jj < 4; ++jj) {
        int j = tc * 4 + jj;
        float cv = g_cvec[b][h][j];
        float4 gv;
        gv.x = gelu_exact(acc[0][jj] + cv);
        gv.y = gelu_exact(acc[1][jj] + cv);
        gv.z = gelu_exact(acc[2][jj] + cv);
        gv.w = gelu_exact(acc[3][jj] + cv);
        *(float4*)&aT[j][tr * 4] = gv;
    }
    for (int idx = tid; idx < 64 * 64; idx += 256) {
        int f = idx >> 6, j = idx & 63;
        bT[j][f] = fuW2[(size_t)(h * HD + f) * HD + j];
    }
    __syncthreads();

    float acc2[4][4];
#pragma unroll
    for (int i = 0; i < 4; ++i)
#pragma unroll
        for (int j = 0; j < 4; ++j) acc2[i][j] = 0.0f;

#pragma unroll
    for (int j = 0; j < HD; ++j) {
        float4 a = *(const float4*)&aT[j][tr * 4];
        float4 bv = *(const float4*)&bT[j][tc * 4];
        float ra[4] = {a.x, a.y, a.z, a.w};
        float rb[4] = {bv.x, bv.y, bv.z, bv.w};
#pragma unroll
        for (int i = 0; i < 4; ++i)
#pragma unroll
            for (int jj = 0; jj < 4; ++jj)
                acc2[i][jj] = fmaf(ra[i], rb[jj], acc2[i][jj]);
    }

    float bias[4];
#pragma unroll
    for (int jj = 0; jj < 4; ++jj) bias[jj] = fub2[h * HD + tc * 4 + jj];

#pragma unroll
    for (int i = 0; i < 4; ++i) {
        int t = tr * 4 + i;
        float x0 = acc2[i][0] + bias[0];
        float x1 = acc2[i][1] + bias[1];
        float x2 = acc2[i][2] + bias[2];
        float x3 = acc2[i][3] + bias[3];
        __nv_bfloat16 h0 = __float2bfloat16_rn(x0);
        __nv_bfloat16 h1 = __float2bfloat16_rn(x1);
        __nv_bfloat16 h2 = __float2bfloat16_rn(x2);
        __nv_bfloat16 h3 = __float2bfloat16_rn(x3);
        __nv_bfloat162 hA = {h0, h1}, hB = {h2, h3};
        __nv_bfloat162 lA = {__float2bfloat16_rn(x0 - __bfloat162float(h0)),
                             __float2bfloat16_rn(x1 - __bfloat162float(h1))};
        __nv_bfloat162 lB = {__float2bfloat16_rn(x2 - __bfloat162float(h2)),
                             __float2bfloat16_rn(x3 - __bfloat162float(h3))};
        size_t base = (size_t)(m0 + t) * K3 + h * HD + tc * 4;
        *(__nv_bfloat162*)&g_multiS[base]                  = hA;
        *(__nv_bfloat162*)&g_multiS[base + 2]              = hB;
        *(__nv_bfloat162*)&g_multiS[base + DMODEL]         = lA;
        *(__nv_bfloat162*)&g_multiS[base + DMODEL + 2]     = lB;
        *(__nv_bfloat162*)&g_multiS[base + 2 * DMODEL]     = hA;
        *(__nv_bfloat162*)&g_multiS[base + 2 * DMODEL + 2] = hB;
    }
}

// ---------------------------------------------------------------------------
// Trivial outputs: fwd/bwd targets + avg_strength (analytic constants)
// ---------------------------------------------------------------------------
__global__ void extras_kernel(const int* __restrict__ prev,
                              const float* __restrict__ cr,
                              float* __restrict__ out)
{
    int idx = blockIdx.x * blockDim.x + threadIdx.x;
    if (idx >= NTOK) return;
    int n = idx & (NSEQ - 1);

    float thr = floorf((float)NSEQ / (1.0f + expf(-cr[0])));
    float fwd = 511.0f;
    if ((float)n >= thr) {
        int p = prev[idx];
        p = p < 0 ? 0 : (p > NSEQ - 1 ? NSEQ - 1 : p);
        fwd = (float)p;
    }
    out[OFF_FWD + idx] = fwd;
    out[OFF_BWD + idx] = 511.0f;
    out[OFF_STR + idx] = 1.0f - logf(1.0f / (float)NSEQ + 1e-8f);
}

// ---------------------------------------------------------------------------
extern "C" void kernel_launch(void* const* d_in, const int* in_sizes, int n_in,
                              void* d_out, int out_size)
{
    const float* h    = (const float*)d_in[0];
    const int*   prev = (const int*)d_in[1];
    // d_in[2..9]: forward/backward encoder weights — provably dead code
    const float* Wv   = (const float*)d_in[10];
    const float* fuW1 = (const float*)d_in[11];
    const float* fub1 = (const float*)d_in[12];
    const float* fuW2 = (const float*)d_in[13];
    const float* fub2 = (const float*)d_in[14];
    const float* Wo   = (const float*)d_in[15];
    const float* cr   = (const float*)d_in[16];
    float* out = (float*)d_out;

    float *pHF = nullptr;
    __nv_bfloat16 *phS = nullptr, *pWvS = nullptr, *pWoS = nullptr, *pMS = nullptr;
    cudaGetSymbolAddress((void**)&pHF, g_HF);
    cudaGetSymbolAddress((void**)&phS, g_hS);
    cudaGetSymbolAddress((void**)&pWvS, g_WvS);
    cudaGetSymbolAddress((void**)&pWoS, g_WoS);
    cudaGetSymbolAddress((void**)&pMS, g_multiS);

    cudaFuncSetAttribute(gemm_bf16_nt,
                         cudaFuncAttributeMaxDynamicSharedMemorySize, GEMM_SMEM);

    // 0) split-precision converts (A-layout for h; B-layout for weights)
    split3_kernel<<<(NTOK * DMODEL / 4 + 255) / 256, 256>>>(
        h, phS, NTOK * DMODEL, DMODEL, 2 * DMODEL);
    split3_kernel<<<(DMODEL * DMODEL / 4 + 255) / 256, 256>>>(
        Wv, pWvS, DMODEL * DMODEL, 2 * DMODEL, DMODEL);
    split3_kernel<<<(DMODEL * DMODEL / 4 + 255) / 256, 256>>>(
        Wo, pWoS, DMODEL * DMODEL, 2 * DMODEL, DMODEL);

    dim3 g1(DMODEL / TILE_N, NTOK / TILE_M);   // (8, 16) = 128 CTAs

    // 1) head_features = h @ Wv^T  (split bf16: hi*hi + lo*hi + hi*lo)
    gemm_bf16_nt<<<g1, 256, GEMM_SMEM>>>(phS, pWvS, pHF, DMODEL);

    // 2) sequence-mean partials per batch
    colmean_kernel<<<dim3(DMODEL / 128, NB, 4), 128>>>();

    // 3) constant part of fusion stage-1
    cvec_kernel<<<dim3(NH, NB), HD>>>(fuW1, fub1);

    // 4) fusion MLP -> g_multiS (split layout)
    fusion_kernel<<<dim3(NTOK / 64, NH), 256>>>(fuW1, fuW2, fub2);

    // 5) final_output = multi @ Wo^T
    gemm_bf16_nt<<<g1, 256, GEMM_SMEM>>>(pMS, pWoS, out, DMODEL);

    // 6) analytic outputs
    extras_kernel<<<(NTOK + 255) / 256, 256>>>(prev, cr, out);
}

// round 9
// speedup vs baseline: 2.4576x; 1.2108x over previous
#include <cuda_runtime.h>
#include <cuda_bf16.h>
#include <math.h>
#include <stdint.h>

#define NTOK 2048   // B*N
#define DMODEL 1024
#define NSEQ 1024
#define NB 2
#define NH 16
#define HD 64
#define K3 (3 * DMODEL)   // extended split-precision K

// Output layout (float32, concatenated in reference return order)
#define OFF_FIN 0
#define OFF_FWD 2097152
#define OFF_BWD 2099200
#define OFF_STR 2101248

// scratch (device globals — no runtime allocation allowed)
__device__ float g_HF[NTOK * DMODEL];                      // head_features fp32
__device__ float g_partial[4][NB][DMODEL];                 // column-sum partials
__device__ float g_cvec[NB][NH][HD];                       // W1_mid_sum @ mean + b1
// split-precision bf16 operands, extended-K layout (rows of length 3*DMODEL)
__device__ alignas(16) __nv_bfloat16 g_hS[NTOK * K3];      // h:  [hi | lo | hi]
__device__ alignas(16) __nv_bfloat16 g_WvS[DMODEL * K3];   // Wv: [hi | hi | lo]
__device__ alignas(16) __nv_bfloat16 g_WoS[DMODEL * K3];   // Wo: [hi | hi | lo]
__device__ alignas(16) __nv_bfloat16 g_multiS[NTOK * K3];  // multi: [hi | lo | hi]

// ---------------------------------------------------------------------------
// fp32 -> split bf16 (hi at k and o_hi2, lo at o_lo) in extended-K rows
// ---------------------------------------------------------------------------
__global__ void split3_kernel(const float* __restrict__ in,
                              __nv_bfloat16* __restrict__ out,
                              int n, int o_lo, int o_hi2)
{
    int i = (blockIdx.x * blockDim.x + threadIdx.x) * 4;
    if (i >= n) return;
    int row = i >> 10;           // K = DMODEL = 1024 per row
    int k = i & 1023;
    float4 v = *(const float4*)(in + i);

    __nv_bfloat16 h0 = __float2bfloat16_rn(v.x);
    __nv_bfloat16 h1 = __float2bfloat16_rn(v.y);
    __nv_bfloat16 h2 = __float2bfloat16_rn(v.z);
    __nv_bfloat16 h3 = __float2bfloat16_rn(v.w);
    __nv_bfloat16 l0 = __float2bfloat16_rn(v.x - __bfloat162float(h0));
    __nv_bfloat16 l1 = __float2bfloat16_rn(v.y - __bfloat162float(h1));
    __nv_bfloat16 l2 = __float2bfloat16_rn(v.z - __bfloat162float(h2));
    __nv_bfloat16 l3 = __float2bfloat16_rn(v.w - __bfloat162float(h3));

    size_t base = (size_t)row * K3 + k;
    __nv_bfloat162 hA = {h0, h1}, hB = {h2, h3};
    __nv_bfloat162 lA = {l0, l1}, lB = {l2, l3};
    *(__nv_bfloat162*)(out + base)              = hA;
    *(__nv_bfloat162*)(out + base + 2)          = hB;
    *(__nv_bfloat162*)(out + base + o_hi2)      = hA;
    *(__nv_bfloat162*)(out + base + o_hi2 + 2)  = hB;
    *(__nv_bfloat162*)(out + base + o_lo)       = lA;
    *(__nv_bfloat162*)(out + base + o_lo + 2)   = lB;
}

// ---------------------------------------------------------------------------
// bf16 mma.sync NT GEMM v4: C[m][n] = sum_k A[m][k]*W[n][k], fp32 accum.
// CTA 128x64, 4 warps (2x2), warp tile 64x32. GBK=64, 3-stage cp.async ring,
// ONE __syncthreads per chunk, register double-buffered ldmatrix fragments.
// XOR-swizzled 128B smem rows (chunk ci ^= row&7): conflict-free, no padding.
// grid 256 CTAs -> ~2 CTAs/SM for cross-CTA latency hiding.
// ---------------------------------------------------------------------------
#define TILE_M 128
#define TILE_N 64
#define GBK 64
#define NCH (K3 / GBK)                 // 48
#define NSTG 3
#define AREG_B (TILE_M * 128)          // 16384 bytes (A region, 128B rows)
#define BREG_B (TILE_N * 128)          //  8192 bytes (B region)
#define STG_BYTES (AREG_B + BREG_B)    // 24576
#define GEMM_SMEM (NSTG * STG_BYTES)   // 73728

__device__ __forceinline__ void cp16(uint32_t s, const void* g) {
    asm volatile("cp.async.cg.shared.global [%0], [%1], 16;\n" :: "r"(s), "l"(g));
}

__global__ __launch_bounds__(128) void gemm_bf16_nt(
    const __nv_bfloat16* __restrict__ A, const __nv_bfloat16* __restrict__ W,
    float* __restrict__ C, int Nn)
{
    extern __shared__ char dsm[];
    const int tid = threadIdx.x;
    const int lane = tid & 31;
    const int w = tid >> 5;
    const int m0 = blockIdx.y * TILE_M;
    const int n0 = blockIdx.x * TILE_N;
    const int wm = (w >> 1) * 64;   // 2 warp rows
    const int wn = (w & 1) * 32;    // 2 warp cols

    const uint32_t sBase = (uint32_t)__cvta_generic_to_shared(dsm);

    // fragment addressing (per-thread invariants)
    const int a_row = wm + (lane & 15);
    const int a_ch = (lane >> 4);          // 16B chunk offset within k-step
    const int b_row = wn + ((lane >> 4) & 1) * 8 + (lane & 7);
    const int b_ch = ((lane >> 3) & 1);

    float acc[4][4][4];
#pragma unroll
    for (int i = 0; i < 4; ++i)
#pragma unroll
        for (int j = 0; j < 4; ++j)
#pragma unroll
            for (int r = 0; r < 4; ++r) acc[i][j][r] = 0.0f;

    auto load_chunk = [&](int ck) {
        int stg = ck % NSTG;
        uint32_t sa = sBase + stg * STG_BYTES;
        uint32_t sb = sa + AREG_B;
        int k0 = ck * GBK;
#pragma unroll
        for (int j = 0; j < 8; ++j) {       // A: 1024 16B-chunks
            int c = tid + j * 128;
            int r = c >> 3;
            int ci = c & 7;
            cp16(sa + r * 128 + ((ci ^ (r & 7)) << 4),
                 A + (size_t)(m0 + r) * K3 + k0 + ci * 8);
        }
#pragma unroll
        for (int j = 0; j < 4; ++j) {       // B: 512 16B-chunks
            int c = tid + j * 128;
            int r = c >> 3;
            int ci = c & 7;
            cp16(sb + r * 128 + ((ci ^ (r & 7)) << 4),
                 W + (size_t)(n0 + r) * K3 + k0 + ci * 8);
        }
        asm volatile("cp.async.commit_group;\n");
    };

    load_chunk(0);
    load_chunk(1);

    for (int it = 0; it < NCH; ++it) {
        if (it < NCH - 1) asm volatile("cp.async.wait_group 1;\n");
        else              asm volatile("cp.async.wait_group 0;\n");
        __syncthreads();
        if (it + 2 < NCH) load_chunk(it + 2);  // overwrites buf consumed at it-1

        const uint32_t sa = sBase + (it % NSTG) * STG_BYTES;
        const uint32_t sb = sa + AREG_B;

        uint32_t af[2][4][4];
        uint32_t bf[2][4][2];

        auto ldfrag = [&](int buf, int ks) {
#pragma unroll
            for (int mi = 0; mi < 4; ++mi) {
                int r = a_row + mi * 16;
                int ci = ks * 2 + a_ch;
                uint32_t addr = sa + r * 128 + ((ci ^ (r & 7)) << 4);
                asm volatile(
                    "ldmatrix.sync.aligned.m8n8.x4.shared.b16 {%0,%1,%2,%3},[%4];\n"
                    : "=r"(af[buf][mi][0]), "=r"(af[buf][mi][1]),
                      "=r"(af[buf][mi][2]), "=r"(af[buf][mi][3])
                    : "r"(addr));
            }
#pragma unroll
            for (int np = 0; np < 2; ++np) {
                int r = b_row + np * 16;
                int ci = ks * 2 + b_ch;
                uint32_t addr = sb + r * 128 + ((ci ^ (r & 7)) << 4);
                uint32_t r0, r1, r2, r3;
                asm volatile(
                    "ldmatrix.sync.aligned.m8n8.x4.shared.b16 {%0,%1,%2,%3},[%4];\n"
                    : "=r"(r0), "=r"(r1), "=r"(r2), "=r"(r3) : "r"(addr));
                bf[buf][np * 2][0] = r0;     bf[buf][np * 2][1] = r1;
                bf[buf][np * 2 + 1][0] = r2; bf[buf][np * 2 + 1][1] = r3;
            }
        };

        ldfrag(0, 0);
#pragma unroll
        for (int ks = 0; ks < 4; ++ks) {
            if (ks < 3) ldfrag((ks + 1) & 1, ks + 1);  // prefetch next k-step
            const int cur = ks & 1;
#pragma unroll
            for (int mi = 0; mi < 4; ++mi)
#pragma unroll
                for (int ni = 0; ni < 4; ++ni) {
                    asm volatile(
                        "mma.sync.aligned.m16n8k16.row.col.f32.bf16.bf16.f32 "
                        "{%0,%1,%2,%3},{%4,%5,%6,%7},{%8,%9},{%0,%1,%2,%3};\n"
                        : "+f"(acc[mi][ni][0]), "+f"(acc[mi][ni][1]),
                          "+f"(acc[mi][ni][2]), "+f"(acc[mi][ni][3])
                        : "r"(af[cur][mi][0]), "r"(af[cur][mi][1]),
                          "r"(af[cur][mi][2]), "r"(af[cur][mi][3]),
                          "r"(bf[cur][ni][0]), "r"(bf[cur][ni][1]));
                }
        }
    }

    // epilogue: c-frag rows g / g+8, cols 2*(lane&3), 2*(lane&3)+1
    const int g = lane >> 2;
    const int cc = (lane & 3) * 2;
#pragma unroll
    for (int mi = 0; mi < 4; ++mi) {
#pragma unroll
        for (int ni = 0; ni < 4; ++ni) {
            int row = m0 + wm + mi * 16 + g;
            int col = n0 + wn + ni * 8 + cc;
            *(float2*)(C + (size_t)row * Nn + col) =
                make_float2(acc[mi][ni][0], acc[mi][ni][1]);
            *(float2*)(C + (size_t)(row + 8) * Nn + col) =
                make_float2(acc[mi][ni][2], acc[mi][ni][3]);
        }
    }
}

// ---------------------------------------------------------------------------
// Column partial sums of g_HF per batch (for the sequence mean)
// ---------------------------------------------------------------------------
__global__ void colmean_kernel()
{
    int c = blockIdx.x * 128 + threadIdx.x;
    int b = blockIdx.y;
    int r = blockIdx.z;
    const float* base = g_HF + (size_t)(b * NSEQ + r * 256) * DMODEL + c;
    float s = 0.0f;
#pragma unroll 4
    for (int row = 0; row < 256; ++row)
        s += base[(size_t)row * DMODEL];
    g_partial[r][b][c] = s;
}

// ---------------------------------------------------------------------------
// cvec[b][h][j] = sum_e (W1[h,j,64+e] + W1[h,j,128+e]) * mean[b][h*64+e] + b1[h,j]
// ---------------------------------------------------------------------------
__global__ void cvec_kernel(const float* __restrict__ fuW1,
                            const float* __restrict__ fub1)
{
    __shared__ float mn[HD];
    int h = blockIdx.x, b = blockIdx.y, j = threadIdx.x;
    int c = h * HD + j;
    mn[j] = (g_partial[0][b][c] + g_partial[1][b][c] +
             g_partial[2][b][c] + g_partial[3][b][c]) * (1.0f / 1024.0f);
    __syncthreads();
    const float* wrow = fuW1 + (size_t)(h * HD + j) * (3 * HD);
    float acc = fub1[h * HD + j];
#pragma unroll
    for (int e = 0; e < HD; ++e)
        acc = fmaf(wrow[64 + e] + wrow[128 + e], mn[e], acc);
    g_cvec[b][h][j] = acc;
}

// ---------------------------------------------------------------------------
// Fusion MLP: per (64-token tile, head): two 64x64x64 GEMMs with exact GELU.
// Writes multi directly in split-precision extended-K layout.
// ---------------------------------------------------------------------------
__device__ __forceinline__ float gelu_exact(float x) {
    return 0.5f * x * (1.0f + erff(x * 0.70710678118654752f));
}

__global__ __launch_bounds__(256) void fusion_kernel(
    const float* __restrict__ fuW1, const float* __restrict__ fuW2,
    const float* __restrict__ fub2)
{
    __shared__ float aT[HD][68];
    __shared__ float bT[HD][68];

    const int tid = threadIdx.x;
    const int m0 = blockIdx.x * 64;
    const int h = blockIdx.y;
    const int b = m0 >> 10;
    const int tr = tid >> 4;
    const int tc = tid & 15;

    for (int idx = tid; idx < 64 * 64; idx += 256) {
        int t = idx >> 6, e = idx & 63;
        aT[e][t] = g_HF[(size_t)(m0 + t) * DMODEL + h * HD + e];
    }
    for (int idx = tid; idx < 64 * 64; idx += 256) {
        int j = idx >> 6, e = idx & 63;
        bT[e][j] = fuW1[(size_t)(h * HD + j) * (3 * HD) + e];
    }
    __syncthreads();

    float acc[4][4];
#pragma unroll
    for (int i = 0; i < 4; ++i)
#pragma unroll
        for (int j = 0; j < 4; ++j) acc[i][j] = 0.0f;

#pragma unroll
    for (int e = 0; e < HD; ++e) {
        float4 a = *(const float4*)&aT[e][tr * 4];
        float4 bv = *(const float4*)&bT[e][tc * 4];
        float ra[4] = {a.x, a.y, a.z, a.w};
        float rb[4] = {bv.x, bv.y, bv.z, bv.w};
#pragma unroll
        for (int i = 0; i < 4; ++i)
#pragma unroll
            for (int j = 0; j < 4; ++j)
                acc[i][j] = fmaf(ra[i], rb[j], acc[i][j]);
    }
    __syncthreads();

#pragma unroll
    for (int jj = 0; jj < 4; ++jj) {
        int j = tc * 4 + jj;
        float cv = g_cvec[b][h][j];
        float4 gv;
        gv.x = gelu_exact(acc[0][jj] + cv);
        gv.y = gelu_exact(acc[1][jj] + cv);
        gv.z = gelu_exact(acc[2][jj] + cv);
        gv.w = gelu_exact(acc[3][jj] + cv);
        *(float4*)&aT[j][tr * 4] = gv;
    }
    for (int idx = tid; idx < 64 * 64; idx += 256) {
        int f = idx >> 6, j = idx & 63;
        bT[j][f] = fuW2[(size_t)(h * HD + f) * HD + j];
    }
    __syncthreads();

    float acc2[4][4];
#pragma unroll
    for (int i = 0; i < 4; ++i)
#pragma unroll
        for (int j = 0; j < 4; ++j) acc2[i][j] = 0.0f;

#pragma unroll
    for (int j = 0; j < HD; ++j) {
        float4 a = *(const float4*)&aT[j][tr * 4];
        float4 bv = *(const float4*)&bT[j][tc * 4];
        float ra[4] = {a.x, a.y, a.z, a.w};
        float rb[4] = {bv.x, bv.y, bv.z, bv.w};
#pragma unroll
        for (int i = 0; i < 4; ++i)
#pragma unroll
            for (int jj = 0; jj < 4; ++jj)
                acc2[i][jj] = fmaf(ra[i], rb[jj], acc2[i][jj]);
    }

    float bias[4];
#pragma unroll
    for (int jj = 0; jj < 4; ++jj) bias[jj] = fub2[h * HD + tc * 4 + jj];

#pragma unroll
    for (int i = 0; i < 4; ++i) {
        int t = tr * 4 + i;
        float x0 = acc2[i][0] + bias[0];
        float x1 = acc2[i][1] + bias[1];
        float x2 = acc2[i][2] + bias[2];
        float x3 = acc2[i][3] + bias[3];
        __nv_bfloat16 h0 = __float2bfloat16_rn(x0);
        __nv_bfloat16 h1 = __float2bfloat16_rn(x1);
        __nv_bfloat16 h2 = __float2bfloat16_rn(x2);
        __nv_bfloat16 h3 = __float2bfloat16_rn(x3);
        __nv_bfloat162 hA = {h0, h1}, hB = {h2, h3};
        __nv_bfloat162 lA = {__float2bfloat16_rn(x0 - __bfloat162float(h0)),
                             __float2bfloat16_rn(x1 - __bfloat162float(h1))};
        __nv_bfloat162 lB = {__float2bfloat16_rn(x2 - __bfloat162float(h2)),
                             __float2bfloat16_rn(x3 - __bfloat162float(h3))};
        size_t base = (size_t)(m0 + t) * K3 + h * HD + tc * 4;
        *(__nv_bfloat162*)&g_multiS[base]                  = hA;
        *(__nv_bfloat162*)&g_multiS[base + 2]              = hB;
        *(__nv_bfloat162*)&g_multiS[base + DMODEL]         = lA;
        *(__nv_bfloat162*)&g_multiS[base + DMODEL + 2]     = lB;
        *(__nv_bfloat162*)&g_multiS[base + 2 * DMODEL]     = hA;
        *(__nv_bfloat162*)&g_multiS[base + 2 * DMODEL + 2] = hB;
    }
}

// ---------------------------------------------------------------------------
// Trivial outputs: fwd/bwd targets + avg_strength (analytic constants)
// ---------------------------------------------------------------------------
__global__ void extras_kernel(const int* __restrict__ prev,
                              const float* __restrict__ cr,
                              float* __restrict__ out)
{
    int idx = blockIdx.x * blockDim.x + threadIdx.x;
    if (idx >= NTOK) return;
    int n = idx & (NSEQ - 1);

    float thr = floorf((float)NSEQ / (1.0f + expf(-cr[0])));
    float fwd = 511.0f;
    if ((float)n >= thr) {
        int p = prev[idx];
        p = p < 0 ? 0 : (p > NSEQ - 1 ? NSEQ - 1 : p);
        fwd = (float)p;
    }
    out[OFF_FWD + idx] = fwd;
    out[OFF_BWD + idx] = 511.0f;
    out[OFF_STR + idx] = 1.0f - logf(1.0f / (float)NSEQ + 1e-8f);
}

// ---------------------------------------------------------------------------
extern "C" void kernel_launch(void* const* d_in, const int* in_sizes, int n_in,
                              void* d_out, int out_size)
{
    const float* h    = (const float*)d_in[0];
    const int*   prev = (const int*)d_in[1];
    // d_in[2..9]: forward/backward encoder weights — provably dead code
    const float* Wv   = (const float*)d_in[10];
    const float* fuW1 = (const float*)d_in[11];
    const float* fub1 = (const float*)d_in[12];
    const float* fuW2 = (const float*)d_in[13];
    const float* fub2 = (const float*)d_in[14];
    const float* Wo   = (const float*)d_in[15];
    const float* cr   = (const float*)d_in[16];
    float* out = (float*)d_out;

    float *pHF = nullptr;
    __nv_bfloat16 *phS = nullptr, *pWvS = nullptr, *pWoS = nullptr, *pMS = nullptr;
    cudaGetSymbolAddress((void**)&pHF, g_HF);
    cudaGetSymbolAddress((void**)&phS, g_hS);
    cudaGetSymbolAddress((void**)&pWvS, g_WvS);
    cudaGetSymbolAddress((void**)&pWoS, g_WoS);
    cudaGetSymbolAddress((void**)&pMS, g_multiS);

    cudaFuncSetAttribute(gemm_bf16_nt,
                         cudaFuncAttributeMaxDynamicSharedMemorySize, GEMM_SMEM);

    // 0) split-precision converts (A-layout for h; B-layout for weights)
    split3_kernel<<<(NTOK * DMODEL / 4 + 255) / 256, 256>>>(
        h, phS, NTOK * DMODEL, DMODEL, 2 * DMODEL);
    split3_kernel<<<(DMODEL * DMODEL / 4 + 255) / 256, 256>>>(
        Wv, pWvS, DMODEL * DMODEL, 2 * DMODEL, DMODEL);
    split3_kernel<<<(DMODEL * DMODEL / 4 + 255) / 256, 256>>>(
        Wo, pWoS, DMODEL * DMODEL, 2 * DMODEL, DMODEL);

    dim3 g1(DMODEL / TILE_N, NTOK / TILE_M);   // (16, 16) = 256 CTAs

    // 1) head_features = h @ Wv^T  (split bf16: hi*hi + lo*hi + hi*lo)
    gemm_bf16_nt<<<g1, 128, GEMM_SMEM>>>(phS, pWvS, pHF, DMODEL);

    // 2) sequence-mean partials per batch
    colmean_kernel<<<dim3(DMODEL / 128, NB, 4), 128>>>();

    // 3) constant part of fusion stage-1
    cvec_kernel<<<dim3(NH, NB), HD>>>(fuW1, fub1);

    // 4) fusion MLP -> g_multiS (split layout)
    fusion_kernel<<<dim3(NTOK / 64, NH), 256>>>(fuW1, fuW2, fub2);

    // 5) final_output = multi @ Wo^T
    gemm_bf16_nt<<<g1, 128, GEMM_SMEM>>>(pMS, pWoS, out, DMODEL);

    // 6) analytic outputs
    extras_kernel<<<(NTOK + 255) / 256, 256>>>(prev, cr, out);
}